// round 10
// baseline (speedup 1.0000x reference)
#include <cuda_runtime.h>
#include <cuda_bf16.h>
#include <math.h>
#include <stdint.h>

// Problem constants
#define NN      8192
#define NFEAT   512
#define NFEXT   128
#define NHID    256
#define NH2     512      // 2*nhid
#define NZ      768      // 3*nhid
#define NCLASS  10
#define NHEADS  8

// ---------------- scratch (device globals; allocation-free) ----------------
__device__ __align__(16) __nv_bfloat16 g_adj_bf[(size_t)NN * NN];  // 128 MB
__device__ __align__(16) __nv_bfloat16 g_b1T_hi[NHID * NN];        // 4 MB
__device__ __align__(16) __nv_bfloat16 g_b1T_lo[NHID * NN];        // 4 MB
__device__ __align__(16) float         g_h1[NN * NHID];            // 8 MB
__device__ __align__(16) __nv_bfloat16 g_b2T_hi[NH2 * NN];         // 8 MB
__device__ __align__(16) __nv_bfloat16 g_b2T_lo[NH2 * NN];         // 8 MB
__device__ __align__(16) float         g_h2[NN * NH2];             // 16 MB
__device__ __align__(16) float         g_part[128 * NH2];

// ============================ helpers ======================================
__device__ __forceinline__ uint32_t s2u(const void* p) {
    uint32_t a;
    asm("{ .reg .u64 t; cvta.to.shared.u64 t, %1; cvt.u32.u64 %0, t; }"
        : "=r"(a) : "l"(p));
    return a;
}
__device__ __forceinline__ uint32_t swz64(uint32_t b) { return b ^ ((b >> 3) & 0x30); }

__device__ __forceinline__ void ldsm4(uint32_t* r, uint32_t a) {
    asm volatile("ldmatrix.sync.aligned.m8n8.x4.shared.b16 {%0,%1,%2,%3}, [%4];"
                 : "=r"(r[0]), "=r"(r[1]), "=r"(r[2]), "=r"(r[3]) : "r"(a));
}
__device__ __forceinline__ void mma16816(float* c, const uint32_t* a,
                                         uint32_t b0, uint32_t b1) {
    asm volatile(
        "mma.sync.aligned.m16n8k16.row.col.f32.bf16.bf16.f32 "
        "{%0,%1,%2,%3}, {%4,%5,%6,%7}, {%8,%9}, {%0,%1,%2,%3};"
        : "+f"(c[0]), "+f"(c[1]), "+f"(c[2]), "+f"(c[3])
        : "r"(a[0]), "r"(a[1]), "r"(a[2]), "r"(a[3]), "r"(b0), "r"(b1));
}

// =================== adj -> bf16 ===========================================
__global__ void tobf16_k(const float* __restrict__ in, __nv_bfloat16* __restrict__ out)
{
    size_t i = ((size_t)blockIdx.x * blockDim.x + threadIdx.x) * 8;
    float4 a = *(const float4*)(in + i);
    float4 b = *(const float4*)(in + i + 4);
    float v[8] = {a.x, a.y, a.z, a.w, b.x, b.y, b.z, b.w};
    uint32_t H[4];
    #pragma unroll
    for (int k = 0; k < 4; k++) {
        __nv_bfloat16 h0 = __float2bfloat16(v[2*k]);
        __nv_bfloat16 h1 = __float2bfloat16(v[2*k+1]);
        H[k] = (uint32_t)__bfloat16_as_ushort(h0) | ((uint32_t)__bfloat16_as_ushort(h1) << 16);
    }
    *(uint4*)(out + i) = make_uint4(H[0], H[1], H[2], H[3]);
}

// =================== bf16 mma.sync GEMM ====================================
// C[NN, Ncols] = relu( A[NN,NN](bf16) @ (Bhi+Blo)^T + bias )
// BM=128, BN=128, BK=32. 128 threads = 4 warps (2Mx2N), warp tile 64x64
// -> 12 ldsm.x4 per 64 MMAs (halved smem-bytes/MAC vs 32x64 tile).
// 4-stage cp.async pipeline, 24KB/stage -> 96KB smem -> 2 CTAs/SM.
#define NSTAGE 4
#define STG_B  24576          // A 8KB + BhiT 8KB + BloT 8KB
#define MM_DSMEM (NSTAGE * STG_B)

__global__ void __launch_bounds__(128, 2)
mma_gemm(const __nv_bfloat16* __restrict__ A,
         const __nv_bfloat16* __restrict__ BhiT,
         const __nv_bfloat16* __restrict__ BloT,
         const float* __restrict__ bias, float* __restrict__ C, int Ncols)
{
    extern __shared__ char smraw[];
    const uint32_t base = s2u(smraw);
    const int tid = threadIdx.x, wid = tid >> 5, lane = tid & 31;
    const int rowBase = blockIdx.y * 128, colBase = blockIdx.x * 128;
    const int wm = (wid & 1) * 64, wn = (wid >> 1) * 64;

    const __nv_bfloat16* srcA = A    + (size_t)rowBase * NN;
    const __nv_bfloat16* srcH = BhiT + (size_t)colBase * NN;
    const __nv_bfloat16* srcL = BloT + (size_t)colBase * NN;

    // Each thread loads its own row (tid) of each 128x32 tile: 4 x 16B chunks.
    const size_t grow = (size_t)tid * NN;
    uint32_t dsw[4];
    #pragma unroll
    for (int q = 0; q < 4; q++) dsw[q] = swz64((uint32_t)(tid * 64 + q * 16));

    auto load_stage = [&](int s, int t) {
        const uint32_t stb = base + s * STG_B;
        const size_t koff = (size_t)t * 32;
        #pragma unroll
        for (int q = 0; q < 4; q++) {
            asm volatile("cp.async.cg.shared.global [%0], [%1], 16;"
                         :: "r"(stb + dsw[q]), "l"(srcA + grow + koff + q * 8) : "memory");
            asm volatile("cp.async.cg.shared.global [%0], [%1], 16;"
                         :: "r"(stb + 8192 + dsw[q]), "l"(srcH + grow + koff + q * 8) : "memory");
            asm volatile("cp.async.cg.shared.global [%0], [%1], 16;"
                         :: "r"(stb + 16384 + dsw[q]), "l"(srcL + grow + koff + q * 8) : "memory");
        }
    };

    #pragma unroll
    for (int s = 0; s < NSTAGE - 1; s++) {
        load_stage(s, s);
        asm volatile("cp.async.commit_group;" ::: "memory");
    }

    float acc[4][8][4];
    #pragma unroll
    for (int i = 0; i < 4; i++)
        #pragma unroll
        for (int j = 0; j < 8; j++)
            #pragma unroll
            for (int k = 0; k < 4; k++) acc[i][j][k] = 0.f;

    const int lr = lane & 15;
    const int lc = (lane >> 4) * 16;
    const int nt = NN / 32;   // 256 k-tiles

    for (int t = 0; t < nt; t++) {
        asm volatile("cp.async.wait_group %0;" :: "n"(NSTAGE - 2) : "memory");
        __syncthreads();

        if (t + NSTAGE - 1 < nt) load_stage((t + NSTAGE - 1) % NSTAGE, t + NSTAGE - 1);
        asm volatile("cp.async.commit_group;" ::: "memory");

        const uint32_t stb = base + (t % NSTAGE) * STG_B;
        #pragma unroll
        for (int ks = 0; ks < 2; ks++) {
            uint32_t afr[4][4];
            #pragma unroll
            for (int mt = 0; mt < 4; mt++)
                ldsm4(afr[mt], stb + swz64((uint32_t)((wm + mt * 16 + lr) * 64 + ks * 32 + lc)));
            #pragma unroll
            for (int g = 0; g < 4; g++) {
                uint32_t bh[4], bl[4];
                const uint32_t so = swz64((uint32_t)((wn + g * 16 + lr) * 64 + ks * 32 + lc));
                ldsm4(bh, stb + 8192 + so);
                ldsm4(bl, stb + 16384 + so);
                #pragma unroll
                for (int mt = 0; mt < 4; mt++)
                    #pragma unroll
                    for (int h = 0; h < 2; h++) {
                        mma16816(acc[mt][g * 2 + h], afr[mt], bh[h], bh[h + 2]);
                        mma16816(acc[mt][g * 2 + h], afr[mt], bl[h], bl[h + 2]);
                    }
            }
        }
    }

    // epilogue: bias + relu, direct fp32 stores
    const int r0e = rowBase + wm + (lane >> 2);
    const int cp0 = colBase + wn + (lane & 3) * 2;
    #pragma unroll
    for (int n8 = 0; n8 < 8; n8++) {
        const int col = cp0 + n8 * 8;
        const float2 bv = *(const float2*)&bias[col];
        #pragma unroll
        for (int mt = 0; mt < 4; mt++) {
            const int row = r0e + mt * 16;
            float2 v0, v1;
            v0.x = fmaxf(acc[mt][n8][0] + bv.x, 0.f);
            v0.y = fmaxf(acc[mt][n8][1] + bv.y, 0.f);
            v1.x = fmaxf(acc[mt][n8][2] + bv.x, 0.f);
            v1.y = fmaxf(acc[mt][n8][3] + bv.y, 0.f);
            *(float2*)&C[(size_t)row * Ncols + col]       = v0;
            *(float2*)&C[(size_t)(row + 8) * Ncols + col] = v1;
        }
    }
}

// =================== fp32 SIMT GEMM, epilogue -> transposed bf16 hi/lo =====
// Computes P = A[M,K] @ B[K,N] (fp32) and writes hiT/loT [N, M] bf16 directly.
__global__ void __launch_bounds__(256, 2)
sgemmT_k(const float* __restrict__ A, const float* __restrict__ B,
         __nv_bfloat16* __restrict__ hiT, __nv_bfloat16* __restrict__ loT,
         int M, int N, int K)
{
    const int BM = 128, BN = 64, BK = 16;
    __shared__ __align__(16) float As[2][BK][BM];
    __shared__ __align__(16) float Bs[2][BK][BN];

    const int tid = threadIdx.x;
    const int tx  = tid & 15;
    const int ty  = tid >> 4;
    const int rowBase = blockIdx.y * BM;
    const int colBase = blockIdx.x * BN;
    const int nt = K / BK;

    const int ar0 = (tid)       >> 2;
    const int ak0 = ((tid)  & 3) * 4;
    const int ar1 = (tid + 256) >> 2;
    const int ak1 = ((tid + 256) & 3) * 4;
    const int br  = tid >> 4;
    const int bc  = (tid & 15) * 4;

    {
        float4 va0 = *(const float4*)&A[(size_t)(rowBase + ar0) * K + ak0];
        float4 va1 = *(const float4*)&A[(size_t)(rowBase + ar1) * K + ak1];
        As[0][ak0 + 0][ar0] = va0.x; As[0][ak0 + 1][ar0] = va0.y;
        As[0][ak0 + 2][ar0] = va0.z; As[0][ak0 + 3][ar0] = va0.w;
        As[0][ak1 + 0][ar1] = va1.x; As[0][ak1 + 1][ar1] = va1.y;
        As[0][ak1 + 2][ar1] = va1.z; As[0][ak1 + 3][ar1] = va1.w;
        float4 vb = *(const float4*)&B[(size_t)br * N + colBase + bc];
        *(float4*)&Bs[0][br][bc] = vb;
    }
    __syncthreads();

    float acc[8][4];
    #pragma unroll
    for (int i = 0; i < 8; i++)
        #pragma unroll
        for (int j = 0; j < 4; j++) acc[i][j] = 0.0f;

    int buf = 0;
    for (int t = 0; t < nt; t++) {
        float4 pa0, pa1, pb;
        if (t + 1 < nt) {
            const int koff = (t + 1) * BK;
            pa0 = *(const float4*)&A[(size_t)(rowBase + ar0) * K + koff + ak0];
            pa1 = *(const float4*)&A[(size_t)(rowBase + ar1) * K + koff + ak1];
            pb  = *(const float4*)&B[(size_t)(koff + br) * N + colBase + bc];
        }
        #pragma unroll
        for (int k = 0; k < BK; k++) {
            float a[8], b[4];
            *(float4*)&a[0] = *(float4*)&As[buf][k][ty * 8];
            *(float4*)&a[4] = *(float4*)&As[buf][k][ty * 8 + 4];
            *(float4*)&b[0] = *(float4*)&Bs[buf][k][tx * 4];
            #pragma unroll
            for (int i = 0; i < 8; i++)
                #pragma unroll
                for (int j = 0; j < 4; j++)
                    acc[i][j] = fmaf(a[i], b[j], acc[i][j]);
        }
        if (t + 1 < nt) {
            const int nb = buf ^ 1;
            As[nb][ak0 + 0][ar0] = pa0.x; As[nb][ak0 + 1][ar0] = pa0.y;
            As[nb][ak0 + 2][ar0] = pa0.z; As[nb][ak0 + 3][ar0] = pa0.w;
            As[nb][ak1 + 0][ar1] = pa1.x; As[nb][ak1 + 1][ar1] = pa1.y;
            As[nb][ak1 + 2][ar1] = pa1.z; As[nb][ak1 + 3][ar1] = pa1.w;
            *(float4*)&Bs[nb][br][bc] = pb;
            buf = nb;
        }
        __syncthreads();
    }

    // Transposed hi/lo epilogue: thread owns rows [rowBase+ty*8, +8), cols tx*4..+3.
    #pragma unroll
    for (int j = 0; j < 4; j++) {
        const int col = colBase + tx * 4 + j;
        ushort hi8[8], lo8[8];
        #pragma unroll
        for (int i = 0; i < 8; i++) {
            float v = acc[i][j];
            __nv_bfloat16 h = __float2bfloat16(v);
            __nv_bfloat16 l = __float2bfloat16(v - __bfloat162float(h));
            hi8[i] = __bfloat16_as_ushort(h);
            lo8[i] = __bfloat16_as_ushort(l);
        }
        const size_t o = (size_t)col * NN + rowBase + ty * 8;
        *(uint4*)(hiT + o) = *(const uint4*)hi8;
        *(uint4*)(loT + o) = *(const uint4*)lo8;
    }
}

// =================== pooling + head ========================================
__global__ void colpart_k(const float* __restrict__ h2, float* __restrict__ part)
{
    const int b = blockIdx.x;
    const int t = threadIdx.x;
    const float* base = h2 + (size_t)b * 64 * NH2;
    float s0 = 0.f, s1 = 0.f;
    #pragma unroll 4
    for (int r = 0; r < 64; r++) {
        s0 += base[r * NH2 + t];
        s1 += base[r * NH2 + t + 256];
    }
    part[b * NH2 + t]       = s0;
    part[b * NH2 + t + 256] = s1;
}

__global__ void head_k(const float* __restrict__ part,
                       const float* __restrict__ sub_fea,
                       const float* __restrict__ fc1W, const float* __restrict__ fc1b,
                       const float* __restrict__ attW, const float* __restrict__ atta,
                       const float* __restrict__ attb, float* __restrict__ out)
{
    __shared__ float z[NZ];
    __shared__ float sc[NHEADS];
    __shared__ float alpha[NHEADS];
    __shared__ float redAll[256][NCLASS];

    const int t = threadIdx.x;

    float s0 = 0.f, s1 = 0.f;
    for (int b = 0; b < 128; b++) {
        s0 += part[b * NH2 + t];
        s1 += part[b * NH2 + t + 256];
    }
    const float selu_s = 1.0507009873554805f;
    const float selu_a = 1.6732632423543772f;
    float m0 = s0 * (1.0f / NN), m1 = s1 * (1.0f / NN);
    z[t]       = (m0 > 0.f) ? selu_s * m0 : selu_s * selu_a * (expf(m0) - 1.f);
    z[t + 256] = (m1 > 0.f) ? selu_s * m1 : selu_s * selu_a * (expf(m1) - 1.f);

    float xe = fc1b[t];
    #pragma unroll 4
    for (int i = 0; i < NFEXT; i++)
        xe = fmaf(sub_fea[i], fc1W[i * NHID + t], xe);
    z[512 + t] = xe;
    __syncthreads();

    const int w = t >> 5, lane = t & 31;
    if (w < NHEADS) {
        float s = 0.f;
        for (int i = lane; i < NZ; i += 32)
            s = fmaf(z[i], atta[w * NZ + i], s);
        #pragma unroll
        for (int o = 16; o > 0; o >>= 1) s += __shfl_xor_sync(0xffffffffu, s, o);
        if (lane == 0) sc[w] = s;
    }
    __syncthreads();
    if (t == 0) {
        float mx = sc[0];
        for (int h = 1; h < NHEADS; h++) mx = fmaxf(mx, sc[h]);
        float den = 0.f;
        for (int h = 0; h < NHEADS; h++) { alpha[h] = expf(sc[h] - mx); den += alpha[h]; }
        float inv = 1.f / den;
        for (int h = 0; h < NHEADS; h++) alpha[h] *= inv;
    }
    __syncthreads();

    float acc[NCLASS];
    #pragma unroll
    for (int o = 0; o < NCLASS; o++) acc[o] = 0.f;
    for (int idx = t; idx < NHEADS * NZ; idx += 256) {
        const int h = idx / NZ;
        const int i = idx - h * NZ;
        const float wz = alpha[h] * z[i];
        const float* wp = attW + (size_t)idx * NCLASS;
        #pragma unroll
        for (int o = 0; o < NCLASS; o++) acc[o] = fmaf(wz, wp[o], acc[o]);
    }
    #pragma unroll
    for (int o = 0; o < NCLASS; o++) redAll[t][o] = acc[o];
    __syncthreads();

    if (t == 0) {
        float v[NCLASS];
        float mx = -1e30f;
        for (int o = 0; o < NCLASS; o++) {
            float s = 0.f;
            for (int i = 0; i < 256; i++) s += redAll[i][o];
            v[o] = s + attb[o];
            mx = fmaxf(mx, v[o]);
        }
        float den = 0.f;
        for (int o = 0; o < NCLASS; o++) den += expf(v[o] - mx);
        float lse = logf(den) + mx;
        for (int o = 0; o < NCLASS; o++) out[o] = v[o] - lse;
    }
}

// ===========================================================================
extern "C" void kernel_launch(void* const* d_in, const int* in_sizes, int n_in,
                              void* d_out, int out_size)
{
    const float* x      = (const float*)d_in[0];
    const float* adj    = (const float*)d_in[1];
    const float* subfea = (const float*)d_in[2];
    const float* gc1W   = (const float*)d_in[3];
    const float* gc1b   = (const float*)d_in[4];
    const float* gc2W   = (const float*)d_in[5];
    const float* gc2b   = (const float*)d_in[6];
    const float* fc1W   = (const float*)d_in[7];
    const float* fc1b   = (const float*)d_in[8];
    const float* attW   = (const float*)d_in[9];
    const float* atta   = (const float*)d_in[10];
    const float* attb   = (const float*)d_in[11];
    float* out = (float*)d_out;

    __nv_bfloat16 *adjbf, *b1Thi, *b1Tlo, *b2Thi, *b2Tlo;
    float *h1, *h2, *part;
    cudaGetSymbolAddress((void**)&adjbf, g_adj_bf);
    cudaGetSymbolAddress((void**)&b1Thi, g_b1T_hi);
    cudaGetSymbolAddress((void**)&b1Tlo, g_b1T_lo);
    cudaGetSymbolAddress((void**)&h1,    g_h1);
    cudaGetSymbolAddress((void**)&b2Thi, g_b2T_hi);
    cudaGetSymbolAddress((void**)&b2Tlo, g_b2T_lo);
    cudaGetSymbolAddress((void**)&h2,    g_h2);
    cudaGetSymbolAddress((void**)&part,  g_part);

    cudaFuncSetAttribute(mma_gemm, cudaFuncAttributeMaxDynamicSharedMemorySize, MM_DSMEM);

    // adj -> bf16 (64M elems, 8/thread)
    tobf16_k<<<(NN * (size_t)NN) / (8 * 256), 256>>>(adj, adjbf);

    // xw1 = x @ gc1_W, fused transposed bf16 hi/lo output
    sgemmT_k<<<dim3(NHID / 64, NN / 128), 256>>>(
        x, gc1W, b1Thi, b1Tlo, NN, NHID, NFEAT);

    // h1 = relu(adj @ xw1 + gc1_b)  — bf16 mma.sync, B hi/lo split
    mma_gemm<<<dim3(NHID / 128, NN / 128), 128, MM_DSMEM>>>(
        adjbf, b1Thi, b1Tlo, gc1b, h1, NHID);

    // hw2 = h1 @ gc2_W, fused transposed bf16 hi/lo output
    sgemmT_k<<<dim3(NH2 / 64, NN / 128), 256>>>(
        h1, gc2W, b2Thi, b2Tlo, NN, NH2, NHID);

    // h2 = relu(adj @ hw2 + gc2_b)  — bf16 mma.sync, B hi/lo split
    mma_gemm<<<dim3(NH2 / 128, NN / 128), 128, MM_DSMEM>>>(
        adjbf, b2Thi, b2Tlo, gc2b, h2, NH2);

    // pooling + head
    colpart_k<<<128, 256>>>(h2, part);
    head_k<<<1, 256>>>(part, subfea, fc1W, fc1b, attW, atta, attb, out);
}

// round 11
// speedup vs baseline: 1.2484x; 1.2484x over previous
#include <cuda_runtime.h>
#include <cuda_bf16.h>
#include <math.h>
#include <stdint.h>

// Problem constants
#define NN      8192
#define NFEAT   512
#define NFEXT   128
#define NHID    256
#define NH2     512      // 2*nhid
#define NZ      768      // 3*nhid
#define NCLASS  10
#define NHEADS  8

// ---------------- scratch (device globals; allocation-free) ----------------
__device__ __align__(16) __nv_bfloat16 g_adj_bf[(size_t)NN * NN];  // 128 MB
__device__ __align__(16) __nv_bfloat16 g_b1T_hi[NHID * NN];        // 4 MB
__device__ __align__(16) __nv_bfloat16 g_b1T_lo[NHID * NN];        // 4 MB
__device__ __align__(16) float         g_h1[NN * NHID];            // 8 MB
__device__ __align__(16) __nv_bfloat16 g_b2T_hi[NH2 * NN];         // 8 MB
__device__ __align__(16) __nv_bfloat16 g_b2T_lo[NH2 * NN];         // 8 MB
__device__ __align__(16) float         g_h2[NN * NH2];             // 16 MB
__device__ __align__(16) float         g_part[128 * NH2];

// ============================ helpers ======================================
__device__ __forceinline__ uint32_t s2u(const void* p) {
    uint32_t a;
    asm("{ .reg .u64 t; cvta.to.shared.u64 t, %1; cvt.u32.u64 %0, t; }"
        : "=r"(a) : "l"(p));
    return a;
}
__device__ __forceinline__ uint32_t swz64(uint32_t b) { return b ^ ((b >> 3) & 0x30); }

__device__ __forceinline__ void ldsm4(uint32_t* r, uint32_t a) {
    asm volatile("ldmatrix.sync.aligned.m8n8.x4.shared.b16 {%0,%1,%2,%3}, [%4];"
                 : "=r"(r[0]), "=r"(r[1]), "=r"(r[2]), "=r"(r[3]) : "r"(a));
}
__device__ __forceinline__ void mma16816(float* c, const uint32_t* a,
                                         uint32_t b0, uint32_t b1) {
    asm volatile(
        "mma.sync.aligned.m16n8k16.row.col.f32.bf16.bf16.f32 "
        "{%0,%1,%2,%3}, {%4,%5,%6,%7}, {%8,%9}, {%0,%1,%2,%3};"
        : "+f"(c[0]), "+f"(c[1]), "+f"(c[2]), "+f"(c[3])
        : "r"(a[0]), "r"(a[1]), "r"(a[2]), "r"(a[3]), "r"(b0), "r"(b1));
}

// =================== adj -> bf16 ===========================================
__global__ void tobf16_k(const float* __restrict__ in, __nv_bfloat16* __restrict__ out)
{
    size_t i = ((size_t)blockIdx.x * blockDim.x + threadIdx.x) * 8;
    float4 a = *(const float4*)(in + i);
    float4 b = *(const float4*)(in + i + 4);
    float v[8] = {a.x, a.y, a.z, a.w, b.x, b.y, b.z, b.w};
    uint32_t H[4];
    #pragma unroll
    for (int k = 0; k < 4; k++) {
        __nv_bfloat16 h0 = __float2bfloat16(v[2*k]);
        __nv_bfloat16 h1 = __float2bfloat16(v[2*k+1]);
        H[k] = (uint32_t)__bfloat16_as_ushort(h0) | ((uint32_t)__bfloat16_as_ushort(h1) << 16);
    }
    *(uint4*)(out + i) = make_uint4(H[0], H[1], H[2], H[3]);
}

// =================== bf16 mma.sync GEMM ====================================
// C[NN, Ncols] = relu( A[NN,NN](bf16) @ (Bhi+Blo)^T + bias )
// BM=128, BN=128, BK=32. 256 threads, 8 warps as 2M x 4N -> warp tile 64x32.
// Per k16: 4 A-ldsm + 4 B-ldsm for 32 MMAs (B, the hi/lo-doubled operand,
// gets minimal ldsm). acc=64 regs -> ~115 total, fits occupancy 2.
// 4-stage cp.async pipeline, 24KB/stage -> 96KB smem -> 2 CTAs/SM.
#define NSTAGE 4
#define STG_B  24576          // A 8KB + BhiT 8KB + BloT 8KB
#define MM_DSMEM (NSTAGE * STG_B)

__global__ void __launch_bounds__(256, 2)
mma_gemm(const __nv_bfloat16* __restrict__ A,
         const __nv_bfloat16* __restrict__ BhiT,
         const __nv_bfloat16* __restrict__ BloT,
         const float* __restrict__ bias, float* __restrict__ C, int Ncols)
{
    extern __shared__ char smraw[];
    const uint32_t base = s2u(smraw);
    const int tid = threadIdx.x, wid = tid >> 5, lane = tid & 31;
    const int rowBase = blockIdx.y * 128, colBase = blockIdx.x * 128;
    const int wm = (wid & 1) * 64, wn = (wid >> 1) * 32;

    const __nv_bfloat16* srcA = A    + (size_t)rowBase * NN;
    const __nv_bfloat16* srcH = BhiT + (size_t)colBase * NN;
    const __nv_bfloat16* srcL = BloT + (size_t)colBase * NN;

    // 128 rows x 4 chunks (16B) per matrix = 512 chunks; 2 per thread.
    const int c0 = tid * 2, c1 = tid * 2 + 1;
    const int r0 = c0 >> 2, j0 = c0 & 3;
    const int r1 = c1 >> 2, j1 = c1 & 3;
    const uint32_t d0 = swz64((uint32_t)(r0 * 64 + j0 * 16));
    const uint32_t d1 = swz64((uint32_t)(r1 * 64 + j1 * 16));
    const size_t g0 = (size_t)r0 * NN + j0 * 8;
    const size_t g1 = (size_t)r1 * NN + j1 * 8;

    auto load_stage = [&](int s, int t) {
        const uint32_t stb = base + s * STG_B;
        const size_t koff = (size_t)t * 32;
        asm volatile("cp.async.cg.shared.global [%0], [%1], 16;"
                     :: "r"(stb + d0), "l"(srcA + g0 + koff) : "memory");
        asm volatile("cp.async.cg.shared.global [%0], [%1], 16;"
                     :: "r"(stb + d1), "l"(srcA + g1 + koff) : "memory");
        asm volatile("cp.async.cg.shared.global [%0], [%1], 16;"
                     :: "r"(stb + 8192 + d0), "l"(srcH + g0 + koff) : "memory");
        asm volatile("cp.async.cg.shared.global [%0], [%1], 16;"
                     :: "r"(stb + 8192 + d1), "l"(srcH + g1 + koff) : "memory");
        asm volatile("cp.async.cg.shared.global [%0], [%1], 16;"
                     :: "r"(stb + 16384 + d0), "l"(srcL + g0 + koff) : "memory");
        asm volatile("cp.async.cg.shared.global [%0], [%1], 16;"
                     :: "r"(stb + 16384 + d1), "l"(srcL + g1 + koff) : "memory");
    };

    #pragma unroll
    for (int s = 0; s < NSTAGE - 1; s++) {
        load_stage(s, s);
        asm volatile("cp.async.commit_group;" ::: "memory");
    }

    float acc[4][4][4];
    #pragma unroll
    for (int i = 0; i < 4; i++)
        #pragma unroll
        for (int j = 0; j < 4; j++)
            #pragma unroll
            for (int k = 0; k < 4; k++) acc[i][j][k] = 0.f;

    const int lr = lane & 15;
    const int lc = (lane >> 4) * 16;
    const int nt = NN / 32;   // 256 k-tiles

    for (int t = 0; t < nt; t++) {
        asm volatile("cp.async.wait_group %0;" :: "n"(NSTAGE - 2) : "memory");
        __syncthreads();

        if (t + NSTAGE - 1 < nt) load_stage((t + NSTAGE - 1) % NSTAGE, t + NSTAGE - 1);
        asm volatile("cp.async.commit_group;" ::: "memory");

        const uint32_t stb = base + (t % NSTAGE) * STG_B;
        #pragma unroll
        for (int ks = 0; ks < 2; ks++) {
            uint32_t afr[4][4];
            #pragma unroll
            for (int mt = 0; mt < 4; mt++)
                ldsm4(afr[mt], stb + swz64((uint32_t)((wm + mt * 16 + lr) * 64 + ks * 32 + lc)));
            #pragma unroll
            for (int g = 0; g < 2; g++) {
                uint32_t bh[4], bl[4];
                const uint32_t so = swz64((uint32_t)((wn + g * 16 + lr) * 64 + ks * 32 + lc));
                ldsm4(bh, stb + 8192 + so);
                ldsm4(bl, stb + 16384 + so);
                #pragma unroll
                for (int mt = 0; mt < 4; mt++)
                    #pragma unroll
                    for (int h = 0; h < 2; h++) {
                        mma16816(acc[mt][g * 2 + h], afr[mt], bh[h], bh[h + 2]);
                        mma16816(acc[mt][g * 2 + h], afr[mt], bl[h], bl[h + 2]);
                    }
            }
        }
    }

    // epilogue: bias + relu, direct fp32 stores
    const int r0e = rowBase + wm + (lane >> 2);
    const int cp0 = colBase + wn + (lane & 3) * 2;
    #pragma unroll
    for (int n8 = 0; n8 < 4; n8++) {
        const int col = cp0 + n8 * 8;
        const float2 bv = *(const float2*)&bias[col];
        #pragma unroll
        for (int mt = 0; mt < 4; mt++) {
            const int row = r0e + mt * 16;
            float2 v0, v1;
            v0.x = fmaxf(acc[mt][n8][0] + bv.x, 0.f);
            v0.y = fmaxf(acc[mt][n8][1] + bv.y, 0.f);
            v1.x = fmaxf(acc[mt][n8][2] + bv.x, 0.f);
            v1.y = fmaxf(acc[mt][n8][3] + bv.y, 0.f);
            *(float2*)&C[(size_t)row * Ncols + col]       = v0;
            *(float2*)&C[(size_t)(row + 8) * Ncols + col] = v1;
        }
    }
}

// =================== fp32 SIMT GEMM, epilogue -> transposed bf16 hi/lo =====
// Computes P = A[M,K] @ B[K,N] (fp32) and writes hiT/loT [N, M] bf16 directly.
__global__ void __launch_bounds__(256, 2)
sgemmT_k(const float* __restrict__ A, const float* __restrict__ B,
         __nv_bfloat16* __restrict__ hiT, __nv_bfloat16* __restrict__ loT,
         int M, int N, int K)
{
    const int BM = 128, BN = 64, BK = 16;
    __shared__ __align__(16) float As[2][BK][BM];
    __shared__ __align__(16) float Bs[2][BK][BN];

    const int tid = threadIdx.x;
    const int tx  = tid & 15;
    const int ty  = tid >> 4;
    const int rowBase = blockIdx.y * BM;
    const int colBase = blockIdx.x * BN;
    const int nt = K / BK;

    const int ar0 = (tid)       >> 2;
    const int ak0 = ((tid)  & 3) * 4;
    const int ar1 = (tid + 256) >> 2;
    const int ak1 = ((tid + 256) & 3) * 4;
    const int br  = tid >> 4;
    const int bc  = (tid & 15) * 4;

    {
        float4 va0 = *(const float4*)&A[(size_t)(rowBase + ar0) * K + ak0];
        float4 va1 = *(const float4*)&A[(size_t)(rowBase + ar1) * K + ak1];
        As[0][ak0 + 0][ar0] = va0.x; As[0][ak0 + 1][ar0] = va0.y;
        As[0][ak0 + 2][ar0] = va0.z; As[0][ak0 + 3][ar0] = va0.w;
        As[0][ak1 + 0][ar1] = va1.x; As[0][ak1 + 1][ar1] = va1.y;
        As[0][ak1 + 2][ar1] = va1.z; As[0][ak1 + 3][ar1] = va1.w;
        float4 vb = *(const float4*)&B[(size_t)br * N + colBase + bc];
        *(float4*)&Bs[0][br][bc] = vb;
    }
    __syncthreads();

    float acc[8][4];
    #pragma unroll
    for (int i = 0; i < 8; i++)
        #pragma unroll
        for (int j = 0; j < 4; j++) acc[i][j] = 0.0f;

    int buf = 0;
    for (int t = 0; t < nt; t++) {
        float4 pa0, pa1, pb;
        if (t + 1 < nt) {
            const int koff = (t + 1) * BK;
            pa0 = *(const float4*)&A[(size_t)(rowBase + ar0) * K + koff + ak0];
            pa1 = *(const float4*)&A[(size_t)(rowBase + ar1) * K + koff + ak1];
            pb  = *(const float4*)&B[(size_t)(koff + br) * N + colBase + bc];
        }
        #pragma unroll
        for (int k = 0; k < BK; k++) {
            float a[8], b[4];
            *(float4*)&a[0] = *(float4*)&As[buf][k][ty * 8];
            *(float4*)&a[4] = *(float4*)&As[buf][k][ty * 8 + 4];
            *(float4*)&b[0] = *(float4*)&Bs[buf][k][tx * 4];
            #pragma unroll
            for (int i = 0; i < 8; i++)
                #pragma unroll
                for (int j = 0; j < 4; j++)
                    acc[i][j] = fmaf(a[i], b[j], acc[i][j]);
        }
        if (t + 1 < nt) {
            const int nb = buf ^ 1;
            As[nb][ak0 + 0][ar0] = pa0.x; As[nb][ak0 + 1][ar0] = pa0.y;
            As[nb][ak0 + 2][ar0] = pa0.z; As[nb][ak0 + 3][ar0] = pa0.w;
            As[nb][ak1 + 0][ar1] = pa1.x; As[nb][ak1 + 1][ar1] = pa1.y;
            As[nb][ak1 + 2][ar1] = pa1.z; As[nb][ak1 + 3][ar1] = pa1.w;
            *(float4*)&Bs[nb][br][bc] = pb;
            buf = nb;
        }
        __syncthreads();
    }

    // Transposed hi/lo epilogue: thread owns rows [rowBase+ty*8, +8), cols tx*4..+3.
    #pragma unroll
    for (int j = 0; j < 4; j++) {
        const int col = colBase + tx * 4 + j;
        ushort hi8[8], lo8[8];
        #pragma unroll
        for (int i = 0; i < 8; i++) {
            float v = acc[i][j];
            __nv_bfloat16 h = __float2bfloat16(v);
            __nv_bfloat16 l = __float2bfloat16(v - __bfloat162float(h));
            hi8[i] = __bfloat16_as_ushort(h);
            lo8[i] = __bfloat16_as_ushort(l);
        }
        const size_t o = (size_t)col * NN + rowBase + ty * 8;
        *(uint4*)(hiT + o) = *(const uint4*)hi8;
        *(uint4*)(loT + o) = *(const uint4*)lo8;
    }
}

// =================== pooling + head ========================================
__global__ void colpart_k(const float* __restrict__ h2, float* __restrict__ part)
{
    const int b = blockIdx.x;
    const int t = threadIdx.x;
    const float* base = h2 + (size_t)b * 64 * NH2;
    float s0 = 0.f, s1 = 0.f;
    #pragma unroll 4
    for (int r = 0; r < 64; r++) {
        s0 += base[r * NH2 + t];
        s1 += base[r * NH2 + t + 256];
    }
    part[b * NH2 + t]       = s0;
    part[b * NH2 + t + 256] = s1;
}

__global__ void head_k(const float* __restrict__ part,
                       const float* __restrict__ sub_fea,
                       const float* __restrict__ fc1W, const float* __restrict__ fc1b,
                       const float* __restrict__ attW, const float* __restrict__ atta,
                       const float* __restrict__ attb, float* __restrict__ out)
{
    __shared__ float z[NZ];
    __shared__ float sc[NHEADS];
    __shared__ float alpha[NHEADS];
    __shared__ float redAll[256][NCLASS];

    const int t = threadIdx.x;

    float s0 = 0.f, s1 = 0.f;
    for (int b = 0; b < 128; b++) {
        s0 += part[b * NH2 + t];
        s1 += part[b * NH2 + t + 256];
    }
    const float selu_s = 1.0507009873554805f;
    const float selu_a = 1.6732632423543772f;
    float m0 = s0 * (1.0f / NN), m1 = s1 * (1.0f / NN);
    z[t]       = (m0 > 0.f) ? selu_s * m0 : selu_s * selu_a * (expf(m0) - 1.f);
    z[t + 256] = (m1 > 0.f) ? selu_s * m1 : selu_s * selu_a * (expf(m1) - 1.f);

    float xe = fc1b[t];
    #pragma unroll 4
    for (int i = 0; i < NFEXT; i++)
        xe = fmaf(sub_fea[i], fc1W[i * NHID + t], xe);
    z[512 + t] = xe;
    __syncthreads();

    const int w = t >> 5, lane = t & 31;
    if (w < NHEADS) {
        float s = 0.f;
        for (int i = lane; i < NZ; i += 32)
            s = fmaf(z[i], atta[w * NZ + i], s);
        #pragma unroll
        for (int o = 16; o > 0; o >>= 1) s += __shfl_xor_sync(0xffffffffu, s, o);
        if (lane == 0) sc[w] = s;
    }
    __syncthreads();
    if (t == 0) {
        float mx = sc[0];
        for (int h = 1; h < NHEADS; h++) mx = fmaxf(mx, sc[h]);
        float den = 0.f;
        for (int h = 0; h < NHEADS; h++) { alpha[h] = expf(sc[h] - mx); den += alpha[h]; }
        float inv = 1.f / den;
        for (int h = 0; h < NHEADS; h++) alpha[h] *= inv;
    }
    __syncthreads();

    float acc[NCLASS];
    #pragma unroll
    for (int o = 0; o < NCLASS; o++) acc[o] = 0.f;
    for (int idx = t; idx < NHEADS * NZ; idx += 256) {
        const int h = idx / NZ;
        const int i = idx - h * NZ;
        const float wz = alpha[h] * z[i];
        const float* wp = attW + (size_t)idx * NCLASS;
        #pragma unroll
        for (int o = 0; o < NCLASS; o++) acc[o] = fmaf(wz, wp[o], acc[o]);
    }
    #pragma unroll
    for (int o = 0; o < NCLASS; o++) redAll[t][o] = acc[o];
    __syncthreads();

    if (t == 0) {
        float v[NCLASS];
        float mx = -1e30f;
        for (int o = 0; o < NCLASS; o++) {
            float s = 0.f;
            for (int i = 0; i < 256; i++) s += redAll[i][o];
            v[o] = s + attb[o];
            mx = fmaxf(mx, v[o]);
        }
        float den = 0.f;
        for (int o = 0; o < NCLASS; o++) den += expf(v[o] - mx);
        float lse = logf(den) + mx;
        for (int o = 0; o < NCLASS; o++) out[o] = v[o] - lse;
    }
}

// ===========================================================================
extern "C" void kernel_launch(void* const* d_in, const int* in_sizes, int n_in,
                              void* d_out, int out_size)
{
    const float* x      = (const float*)d_in[0];
    const float* adj    = (const float*)d_in[1];
    const float* subfea = (const float*)d_in[2];
    const float* gc1W   = (const float*)d_in[3];
    const float* gc1b   = (const float*)d_in[4];
    const float* gc2W   = (const float*)d_in[5];
    const float* gc2b   = (const float*)d_in[6];
    const float* fc1W   = (const float*)d_in[7];
    const float* fc1b   = (const float*)d_in[8];
    const float* attW   = (const float*)d_in[9];
    const float* atta   = (const float*)d_in[10];
    const float* attb   = (const float*)d_in[11];
    float* out = (float*)d_out;

    __nv_bfloat16 *adjbf, *b1Thi, *b1Tlo, *b2Thi, *b2Tlo;
    float *h1, *h2, *part;
    cudaGetSymbolAddress((void**)&adjbf, g_adj_bf);
    cudaGetSymbolAddress((void**)&b1Thi, g_b1T_hi);
    cudaGetSymbolAddress((void**)&b1Tlo, g_b1T_lo);
    cudaGetSymbolAddress((void**)&h1,    g_h1);
    cudaGetSymbolAddress((void**)&b2Thi, g_b2T_hi);
    cudaGetSymbolAddress((void**)&b2Tlo, g_b2T_lo);
    cudaGetSymbolAddress((void**)&h2,    g_h2);
    cudaGetSymbolAddress((void**)&part,  g_part);

    cudaFuncSetAttribute(mma_gemm, cudaFuncAttributeMaxDynamicSharedMemorySize, MM_DSMEM);

    // adj -> bf16 (64M elems, 8/thread)
    tobf16_k<<<(NN * (size_t)NN) / (8 * 256), 256>>>(adj, adjbf);

    // xw1 = x @ gc1_W, fused transposed bf16 hi/lo output
    sgemmT_k<<<dim3(NHID / 64, NN / 128), 256>>>(
        x, gc1W, b1Thi, b1Tlo, NN, NHID, NFEAT);

    // h1 = relu(adj @ xw1 + gc1_b)  — bf16 mma.sync, B hi/lo split
    mma_gemm<<<dim3(NHID / 128, NN / 128), 256, MM_DSMEM>>>(
        adjbf, b1Thi, b1Tlo, gc1b, h1, NHID);

    // hw2 = h1 @ gc2_W, fused transposed bf16 hi/lo output
    sgemmT_k<<<dim3(NH2 / 64, NN / 128), 256>>>(
        h1, gc2W, b2Thi, b2Tlo, NN, NH2, NHID);

    // h2 = relu(adj @ hw2 + gc2_b)  — bf16 mma.sync, B hi/lo split
    mma_gemm<<<dim3(NH2 / 128, NN / 128), 256, MM_DSMEM>>>(
        adjbf, b2Thi, b2Tlo, gc2b, h2, NH2);

    // pooling + head
    colpart_k<<<128, 256>>>(h2, part);
    head_k<<<1, 256>>>(part, subfea, fc1W, fc1b, attW, atta, attb, out);
}

// round 12
// speedup vs baseline: 1.2719x; 1.0188x over previous
#include <cuda_runtime.h>
#include <cuda_bf16.h>
#include <math.h>
#include <stdint.h>

// Problem constants
#define NN      8192
#define NFEAT   512
#define NFEXT   128
#define NHID    256
#define NH2     512      // 2*nhid
#define NZ      768      // 3*nhid
#define NCLASS  10
#define NHEADS  8

// ---------------- scratch (device globals; allocation-free) ----------------
__device__ __align__(16) __nv_bfloat16 g_adj_bf[(size_t)NN * NN];  // 128 MB
__device__ __align__(16) __nv_bfloat16 g_b1T_hi[NHID * NN];        // 4 MB
__device__ __align__(16) __nv_bfloat16 g_b1T_lo[NHID * NN];        // 4 MB
__device__ __align__(16) float         g_h1[NN * NHID];            // 8 MB
__device__ __align__(16) float         g_p1[2u * NN * NHID];       // 16 MB split-K partials
__device__ __align__(16) __nv_bfloat16 g_b2T_hi[NH2 * NN];         // 8 MB
__device__ __align__(16) __nv_bfloat16 g_b2T_lo[NH2 * NN];         // 8 MB
__device__ __align__(16) float         g_h2[NN * NH2];             // 16 MB
__device__ __align__(16) float         g_part[128 * NH2];

// ============================ helpers ======================================
__device__ __forceinline__ uint32_t s2u(const void* p) {
    uint32_t a;
    asm("{ .reg .u64 t; cvta.to.shared.u64 t, %1; cvt.u32.u64 %0, t; }"
        : "=r"(a) : "l"(p));
    return a;
}
__device__ __forceinline__ uint32_t swz64(uint32_t b) { return b ^ ((b >> 3) & 0x30); }

__device__ __forceinline__ void ldsm4(uint32_t* r, uint32_t a) {
    asm volatile("ldmatrix.sync.aligned.m8n8.x4.shared.b16 {%0,%1,%2,%3}, [%4];"
                 : "=r"(r[0]), "=r"(r[1]), "=r"(r[2]), "=r"(r[3]) : "r"(a));
}
__device__ __forceinline__ void mma16816(float* c, const uint32_t* a,
                                         uint32_t b0, uint32_t b1) {
    asm volatile(
        "mma.sync.aligned.m16n8k16.row.col.f32.bf16.bf16.f32 "
        "{%0,%1,%2,%3}, {%4,%5,%6,%7}, {%8,%9}, {%0,%1,%2,%3};"
        : "+f"(c[0]), "+f"(c[1]), "+f"(c[2]), "+f"(c[3])
        : "r"(a[0]), "r"(a[1]), "r"(a[2]), "r"(a[3]), "r"(b0), "r"(b1));
}

// =================== adj -> bf16 ===========================================
__global__ void tobf16_k(const float* __restrict__ in, __nv_bfloat16* __restrict__ out)
{
    size_t i = ((size_t)blockIdx.x * blockDim.x + threadIdx.x) * 8;
    float4 a = *(const float4*)(in + i);
    float4 b = *(const float4*)(in + i + 4);
    float v[8] = {a.x, a.y, a.z, a.w, b.x, b.y, b.z, b.w};
    uint32_t H[4];
    #pragma unroll
    for (int k = 0; k < 4; k++) {
        __nv_bfloat16 h0 = __float2bfloat16(v[2*k]);
        __nv_bfloat16 h1 = __float2bfloat16(v[2*k+1]);
        H[k] = (uint32_t)__bfloat16_as_ushort(h0) | ((uint32_t)__bfloat16_as_ushort(h1) << 16);
    }
    *(uint4*)(out + i) = make_uint4(H[0], H[1], H[2], H[3]);
}

// =================== bf16 mma.sync GEMM ====================================
// FINAL=true : C = relu(A @ (Bhi+Blo)^T + bias), full K.
// FINAL=false: Cp[z] = partial over K slice z (fp32, no bias/relu); grid.z=2.
// BM=128, BN=128, BK=32; 8 warps as 2Mx4N (warp tile 64x32); 4-stage cp.async.
#define NSTAGE 4
#define STG_B  24576          // A 8KB + BhiT 8KB + BloT 8KB
#define MM_DSMEM (NSTAGE * STG_B)

template<bool FINAL>
__global__ void __launch_bounds__(256, 2)
mma_gemm(const __nv_bfloat16* __restrict__ A,
         const __nv_bfloat16* __restrict__ BhiT,
         const __nv_bfloat16* __restrict__ BloT,
         const float* __restrict__ bias, float* __restrict__ C, int Ncols)
{
    extern __shared__ char smraw[];
    const uint32_t base = s2u(smraw);
    const int tid = threadIdx.x, wid = tid >> 5, lane = tid & 31;
    const int rowBase = blockIdx.y * 128, colBase = blockIdx.x * 128;
    const int wm = (wid & 1) * 64, wn = (wid >> 1) * 32;
    const size_t kbase = FINAL ? 0 : (size_t)blockIdx.z * (NN / 2);
    const int nt = FINAL ? (NN / 32) : (NN / 64);   // k-tiles in this CTA's slice

    const __nv_bfloat16* srcA = A    + (size_t)rowBase * NN + kbase;
    const __nv_bfloat16* srcH = BhiT + (size_t)colBase * NN + kbase;
    const __nv_bfloat16* srcL = BloT + (size_t)colBase * NN + kbase;

    // 128 rows x 4 chunks (16B) per matrix = 512 chunks; 2 per thread.
    const int c0 = tid * 2, c1 = tid * 2 + 1;
    const int r0 = c0 >> 2, j0 = c0 & 3;
    const int r1 = c1 >> 2, j1 = c1 & 3;
    const uint32_t d0 = swz64((uint32_t)(r0 * 64 + j0 * 16));
    const uint32_t d1 = swz64((uint32_t)(r1 * 64 + j1 * 16));
    const size_t g0 = (size_t)r0 * NN + j0 * 8;
    const size_t g1 = (size_t)r1 * NN + j1 * 8;

    auto load_stage = [&](int s, int t) {
        const uint32_t stb = base + s * STG_B;
        const size_t koff = (size_t)t * 32;
        asm volatile("cp.async.cg.shared.global [%0], [%1], 16;"
                     :: "r"(stb + d0), "l"(srcA + g0 + koff) : "memory");
        asm volatile("cp.async.cg.shared.global [%0], [%1], 16;"
                     :: "r"(stb + d1), "l"(srcA + g1 + koff) : "memory");
        asm volatile("cp.async.cg.shared.global [%0], [%1], 16;"
                     :: "r"(stb + 8192 + d0), "l"(srcH + g0 + koff) : "memory");
        asm volatile("cp.async.cg.shared.global [%0], [%1], 16;"
                     :: "r"(stb + 8192 + d1), "l"(srcH + g1 + koff) : "memory");
        asm volatile("cp.async.cg.shared.global [%0], [%1], 16;"
                     :: "r"(stb + 16384 + d0), "l"(srcL + g0 + koff) : "memory");
        asm volatile("cp.async.cg.shared.global [%0], [%1], 16;"
                     :: "r"(stb + 16384 + d1), "l"(srcL + g1 + koff) : "memory");
    };

    #pragma unroll
    for (int s = 0; s < NSTAGE - 1; s++) {
        load_stage(s, s);
        asm volatile("cp.async.commit_group;" ::: "memory");
    }

    float acc[4][4][4];
    #pragma unroll
    for (int i = 0; i < 4; i++)
        #pragma unroll
        for (int j = 0; j < 4; j++)
            #pragma unroll
            for (int k = 0; k < 4; k++) acc[i][j][k] = 0.f;

    const int lr = lane & 15;
    const int lc = (lane >> 4) * 16;

    for (int t = 0; t < nt; t++) {
        asm volatile("cp.async.wait_group %0;" :: "n"(NSTAGE - 2) : "memory");
        __syncthreads();

        if (t + NSTAGE - 1 < nt) load_stage((t + NSTAGE - 1) % NSTAGE, t + NSTAGE - 1);
        asm volatile("cp.async.commit_group;" ::: "memory");

        const uint32_t stb = base + (t % NSTAGE) * STG_B;
        #pragma unroll
        for (int ks = 0; ks < 2; ks++) {
            uint32_t afr[4][4];
            #pragma unroll
            for (int mt = 0; mt < 4; mt++)
                ldsm4(afr[mt], stb + swz64((uint32_t)((wm + mt * 16 + lr) * 64 + ks * 32 + lc)));
            #pragma unroll
            for (int g = 0; g < 2; g++) {
                uint32_t bh[4], bl[4];
                const uint32_t so = swz64((uint32_t)((wn + g * 16 + lr) * 64 + ks * 32 + lc));
                ldsm4(bh, stb + 8192 + so);
                ldsm4(bl, stb + 16384 + so);
                #pragma unroll
                for (int mt = 0; mt < 4; mt++)
                    #pragma unroll
                    for (int h = 0; h < 2; h++) {
                        mma16816(acc[mt][g * 2 + h], afr[mt], bh[h], bh[h + 2]);
                        mma16816(acc[mt][g * 2 + h], afr[mt], bl[h], bl[h + 2]);
                    }
            }
        }
    }

    // epilogue
    float* Cout = FINAL ? C : (C + (size_t)blockIdx.z * NN * (size_t)Ncols);
    const int r0e = rowBase + wm + (lane >> 2);
    const int cp0 = colBase + wn + (lane & 3) * 2;
    #pragma unroll
    for (int n8 = 0; n8 < 4; n8++) {
        const int col = cp0 + n8 * 8;
        float2 bv = make_float2(0.f, 0.f);
        if (FINAL) bv = *(const float2*)&bias[col];
        #pragma unroll
        for (int mt = 0; mt < 4; mt++) {
            const int row = r0e + mt * 16;
            float2 v0, v1;
            if (FINAL) {
                v0.x = fmaxf(acc[mt][n8][0] + bv.x, 0.f);
                v0.y = fmaxf(acc[mt][n8][1] + bv.y, 0.f);
                v1.x = fmaxf(acc[mt][n8][2] + bv.x, 0.f);
                v1.y = fmaxf(acc[mt][n8][3] + bv.y, 0.f);
            } else {
                v0.x = acc[mt][n8][0]; v0.y = acc[mt][n8][1];
                v1.x = acc[mt][n8][2]; v1.y = acc[mt][n8][3];
            }
            *(float2*)&Cout[(size_t)row * Ncols + col]       = v0;
            *(float2*)&Cout[(size_t)(row + 8) * Ncols + col] = v1;
        }
    }
}

// combine split-K partials: C = relu(p0 + p1 + bias)
__global__ void combine_relu_k(const float* __restrict__ p, const float* __restrict__ bias,
                               float* __restrict__ C, int Ncols)
{
    const size_t i = ((size_t)blockIdx.x * blockDim.x + threadIdx.x) * 4;
    const int col = (int)(i % Ncols);
    float4 a = *(const float4*)(p + i);
    float4 b = *(const float4*)(p + (size_t)NN * Ncols + i);
    float4 bv = *(const float4*)(bias + col);
    float4 v;
    v.x = fmaxf(a.x + b.x + bv.x, 0.f);
    v.y = fmaxf(a.y + b.y + bv.y, 0.f);
    v.z = fmaxf(a.z + b.z + bv.z, 0.f);
    v.w = fmaxf(a.w + b.w + bv.w, 0.f);
    *(float4*)(C + i) = v;
}

// =================== fp32 SIMT GEMM, epilogue -> transposed bf16 hi/lo =====
__global__ void __launch_bounds__(256, 2)
sgemmT_k(const float* __restrict__ A, const float* __restrict__ B,
         __nv_bfloat16* __restrict__ hiT, __nv_bfloat16* __restrict__ loT,
         int M, int N, int K)
{
    const int BM = 128, BN = 64, BK = 16;
    __shared__ __align__(16) float As[2][BK][BM];
    __shared__ __align__(16) float Bs[2][BK][BN];

    const int tid = threadIdx.x;
    const int tx  = tid & 15;
    const int ty  = tid >> 4;
    const int rowBase = blockIdx.y * BM;
    const int colBase = blockIdx.x * BN;
    const int nt = K / BK;

    const int ar0 = (tid)       >> 2;
    const int ak0 = ((tid)  & 3) * 4;
    const int ar1 = (tid + 256) >> 2;
    const int ak1 = ((tid + 256) & 3) * 4;
    const int br  = tid >> 4;
    const int bc  = (tid & 15) * 4;

    {
        float4 va0 = *(const float4*)&A[(size_t)(rowBase + ar0) * K + ak0];
        float4 va1 = *(const float4*)&A[(size_t)(rowBase + ar1) * K + ak1];
        As[0][ak0 + 0][ar0] = va0.x; As[0][ak0 + 1][ar0] = va0.y;
        As[0][ak0 + 2][ar0] = va0.z; As[0][ak0 + 3][ar0] = va0.w;
        As[0][ak1 + 0][ar1] = va1.x; As[0][ak1 + 1][ar1] = va1.y;
        As[0][ak1 + 2][ar1] = va1.z; As[0][ak1 + 3][ar1] = va1.w;
        float4 vb = *(const float4*)&B[(size_t)br * N + colBase + bc];
        *(float4*)&Bs[0][br][bc] = vb;
    }
    __syncthreads();

    float acc[8][4];
    #pragma unroll
    for (int i = 0; i < 8; i++)
        #pragma unroll
        for (int j = 0; j < 4; j++) acc[i][j] = 0.0f;

    int buf = 0;
    for (int t = 0; t < nt; t++) {
        float4 pa0, pa1, pb;
        if (t + 1 < nt) {
            const int koff = (t + 1) * BK;
            pa0 = *(const float4*)&A[(size_t)(rowBase + ar0) * K + koff + ak0];
            pa1 = *(const float4*)&A[(size_t)(rowBase + ar1) * K + koff + ak1];
            pb  = *(const float4*)&B[(size_t)(koff + br) * N + colBase + bc];
        }
        #pragma unroll
        for (int k = 0; k < BK; k++) {
            float a[8], b[4];
            *(float4*)&a[0] = *(float4*)&As[buf][k][ty * 8];
            *(float4*)&a[4] = *(float4*)&As[buf][k][ty * 8 + 4];
            *(float4*)&b[0] = *(float4*)&Bs[buf][k][tx * 4];
            #pragma unroll
            for (int i = 0; i < 8; i++)
                #pragma unroll
                for (int j = 0; j < 4; j++)
                    acc[i][j] = fmaf(a[i], b[j], acc[i][j]);
        }
        if (t + 1 < nt) {
            const int nb = buf ^ 1;
            As[nb][ak0 + 0][ar0] = pa0.x; As[nb][ak0 + 1][ar0] = pa0.y;
            As[nb][ak0 + 2][ar0] = pa0.z; As[nb][ak0 + 3][ar0] = pa0.w;
            As[nb][ak1 + 0][ar1] = pa1.x; As[nb][ak1 + 1][ar1] = pa1.y;
            As[nb][ak1 + 2][ar1] = pa1.z; As[nb][ak1 + 3][ar1] = pa1.w;
            *(float4*)&Bs[nb][br][bc] = pb;
            buf = nb;
        }
        __syncthreads();
    }

    #pragma unroll
    for (int j = 0; j < 4; j++) {
        const int col = colBase + tx * 4 + j;
        ushort hi8[8], lo8[8];
        #pragma unroll
        for (int i = 0; i < 8; i++) {
            float v = acc[i][j];
            __nv_bfloat16 h = __float2bfloat16(v);
            __nv_bfloat16 l = __float2bfloat16(v - __bfloat162float(h));
            hi8[i] = __bfloat16_as_ushort(h);
            lo8[i] = __bfloat16_as_ushort(l);
        }
        const size_t o = (size_t)col * NN + rowBase + ty * 8;
        *(uint4*)(hiT + o) = *(const uint4*)hi8;
        *(uint4*)(loT + o) = *(const uint4*)lo8;
    }
}

// =================== pooling + head ========================================
__global__ void colpart_k(const float* __restrict__ h2, float* __restrict__ part)
{
    const int b = blockIdx.x;
    const int t = threadIdx.x;
    const float* base = h2 + (size_t)b * 64 * NH2;
    float s0 = 0.f, s1 = 0.f;
    #pragma unroll 4
    for (int r = 0; r < 64; r++) {
        s0 += base[r * NH2 + t];
        s1 += base[r * NH2 + t + 256];
    }
    part[b * NH2 + t]       = s0;
    part[b * NH2 + t + 256] = s1;
}

__global__ void head_k(const float* __restrict__ part,
                       const float* __restrict__ sub_fea,
                       const float* __restrict__ fc1W, const float* __restrict__ fc1b,
                       const float* __restrict__ attW, const float* __restrict__ atta,
                       const float* __restrict__ attb, float* __restrict__ out)
{
    __shared__ float z[NZ];
    __shared__ float sc[NHEADS];
    __shared__ float alpha[NHEADS];
    __shared__ float redAll[256][NCLASS];

    const int t = threadIdx.x;

    float s0 = 0.f, s1 = 0.f;
    for (int b = 0; b < 128; b++) {
        s0 += part[b * NH2 + t];
        s1 += part[b * NH2 + t + 256];
    }
    const float selu_s = 1.0507009873554805f;
    const float selu_a = 1.6732632423543772f;
    float m0 = s0 * (1.0f / NN), m1 = s1 * (1.0f / NN);
    z[t]       = (m0 > 0.f) ? selu_s * m0 : selu_s * selu_a * (expf(m0) - 1.f);
    z[t + 256] = (m1 > 0.f) ? selu_s * m1 : selu_s * selu_a * (expf(m1) - 1.f);

    float xe = fc1b[t];
    #pragma unroll 4
    for (int i = 0; i < NFEXT; i++)
        xe = fmaf(sub_fea[i], fc1W[i * NHID + t], xe);
    z[512 + t] = xe;
    __syncthreads();

    const int w = t >> 5, lane = t & 31;
    if (w < NHEADS) {
        float s = 0.f;
        for (int i = lane; i < NZ; i += 32)
            s = fmaf(z[i], atta[w * NZ + i], s);
        #pragma unroll
        for (int o = 16; o > 0; o >>= 1) s += __shfl_xor_sync(0xffffffffu, s, o);
        if (lane == 0) sc[w] = s;
    }
    __syncthreads();
    if (t == 0) {
        float mx = sc[0];
        for (int h = 1; h < NHEADS; h++) mx = fmaxf(mx, sc[h]);
        float den = 0.f;
        for (int h = 0; h < NHEADS; h++) { alpha[h] = expf(sc[h] - mx); den += alpha[h]; }
        float inv = 1.f / den;
        for (int h = 0; h < NHEADS; h++) alpha[h] *= inv;
    }
    __syncthreads();

    float acc[NCLASS];
    #pragma unroll
    for (int o = 0; o < NCLASS; o++) acc[o] = 0.f;
    for (int idx = t; idx < NHEADS * NZ; idx += 256) {
        const int h = idx / NZ;
        const int i = idx - h * NZ;
        const float wz = alpha[h] * z[i];
        const float* wp = attW + (size_t)idx * NCLASS;
        #pragma unroll
        for (int o = 0; o < NCLASS; o++) acc[o] = fmaf(wz, wp[o], acc[o]);
    }
    #pragma unroll
    for (int o = 0; o < NCLASS; o++) redAll[t][o] = acc[o];
    __syncthreads();

    if (t == 0) {
        float v[NCLASS];
        float mx = -1e30f;
        for (int o = 0; o < NCLASS; o++) {
            float s = 0.f;
            for (int i = 0; i < 256; i++) s += redAll[i][o];
            v[o] = s + attb[o];
            mx = fmaxf(mx, v[o]);
        }
        float den = 0.f;
        for (int o = 0; o < NCLASS; o++) den += expf(v[o] - mx);
        float lse = logf(den) + mx;
        for (int o = 0; o < NCLASS; o++) out[o] = v[o] - lse;
    }
}

// ===========================================================================
extern "C" void kernel_launch(void* const* d_in, const int* in_sizes, int n_in,
                              void* d_out, int out_size)
{
    const float* x      = (const float*)d_in[0];
    const float* adj    = (const float*)d_in[1];
    const float* subfea = (const float*)d_in[2];
    const float* gc1W   = (const float*)d_in[3];
    const float* gc1b   = (const float*)d_in[4];
    const float* gc2W   = (const float*)d_in[5];
    const float* gc2b   = (const float*)d_in[6];
    const float* fc1W   = (const float*)d_in[7];
    const float* fc1b   = (const float*)d_in[8];
    const float* attW   = (const float*)d_in[9];
    const float* atta   = (const float*)d_in[10];
    const float* attb   = (const float*)d_in[11];
    float* out = (float*)d_out;

    __nv_bfloat16 *adjbf, *b1Thi, *b1Tlo, *b2Thi, *b2Tlo;
    float *h1, *p1, *h2, *part;
    cudaGetSymbolAddress((void**)&adjbf, g_adj_bf);
    cudaGetSymbolAddress((void**)&b1Thi, g_b1T_hi);
    cudaGetSymbolAddress((void**)&b1Tlo, g_b1T_lo);
    cudaGetSymbolAddress((void**)&h1,    g_h1);
    cudaGetSymbolAddress((void**)&p1,    g_p1);
    cudaGetSymbolAddress((void**)&b2Thi, g_b2T_hi);
    cudaGetSymbolAddress((void**)&b2Tlo, g_b2T_lo);
    cudaGetSymbolAddress((void**)&h2,    g_h2);
    cudaGetSymbolAddress((void**)&part,  g_part);

    cudaFuncSetAttribute(mma_gemm<true>,  cudaFuncAttributeMaxDynamicSharedMemorySize, MM_DSMEM);
    cudaFuncSetAttribute(mma_gemm<false>, cudaFuncAttributeMaxDynamicSharedMemorySize, MM_DSMEM);

    // adj -> bf16 (64M elems, 8/thread)
    tobf16_k<<<(NN * (size_t)NN) / (8 * 256), 256>>>(adj, adjbf);

    // xw1 = x @ gc1_W, fused transposed bf16 hi/lo output
    sgemmT_k<<<dim3(NHID / 64, NN / 128), 256>>>(
        x, gc1W, b1Thi, b1Tlo, NN, NHID, NFEAT);

    // h1 = relu(adj @ xw1 + gc1_b) — split-K x2 (256 CTAs -> 2/SM resident)
    mma_gemm<false><<<dim3(NHID / 128, NN / 128, 2), 256, MM_DSMEM>>>(
        adjbf, b1Thi, b1Tlo, nullptr, p1, NHID);
    combine_relu_k<<<(NN * NHID) / (4 * 256), 256>>>(p1, gc1b, h1, NHID);

    // hw2 = h1 @ gc2_W, fused transposed bf16 hi/lo output
    sgemmT_k<<<dim3(NH2 / 64, NN / 128), 256>>>(
        h1, gc2W, b2Thi, b2Tlo, NN, NH2, NHID);

    // h2 = relu(adj @ hw2 + gc2_b) — single-pass (256 CTAs already resident)
    mma_gemm<true><<<dim3(NH2 / 128, NN / 128), 256, MM_DSMEM>>>(
        adjbf, b2Thi, b2Tlo, gc2b, h2, NH2);

    // pooling + head
    colpart_k<<<128, 256>>>(h2, part);
    head_k<<<1, 256>>>(part, subfea, fc1W, fc1b, attW, atta, attb, out);
}

// round 14
// speedup vs baseline: 1.8765x; 1.4754x over previous
#include <cuda_runtime.h>
#include <cuda_fp16.h>
#include <math.h>
#include <stdint.h>

// Problem constants
#define NN      8192
#define NFEAT   512
#define NFEXT   128
#define NHID    256
#define NH2     512      // 2*nhid
#define NZ      768      // 3*nhid
#define NCLASS  10
#define NHEADS  8

// ---------------- scratch (device globals; allocation-free) ----------------
__device__ __align__(16) __half g_adj_h[(size_t)NN * NN];   // 128 MB
__device__ __align__(16) __half g_b1T[NHID * NN];           // 4 MB
__device__ __align__(16) float  g_h1[NN * NHID];            // 8 MB
__device__ __align__(16) float  g_p1[2u * NN * NHID];       // 16 MB split-K partials
__device__ __align__(16) __half g_b2T[NH2 * NN];            // 8 MB
__device__ __align__(16) float  g_h2[NN * NH2];             // 16 MB
__device__ __align__(16) float  g_part[128 * NH2];

// ============================ helpers ======================================
__device__ __forceinline__ uint32_t s2u(const void* p) {
    uint32_t a;
    asm("{ .reg .u64 t; cvta.to.shared.u64 t, %1; cvt.u32.u64 %0, t; }"
        : "=r"(a) : "l"(p));
    return a;
}
__device__ __forceinline__ uint32_t swz64(uint32_t b) { return b ^ ((b >> 3) & 0x30); }

__device__ __forceinline__ void ldsm4(uint32_t* r, uint32_t a) {
    asm volatile("ldmatrix.sync.aligned.m8n8.x4.shared.b16 {%0,%1,%2,%3}, [%4];"
                 : "=r"(r[0]), "=r"(r[1]), "=r"(r[2]), "=r"(r[3]) : "r"(a));
}
__device__ __forceinline__ void mma16816h(float* c, const uint32_t* a,
                                          uint32_t b0, uint32_t b1) {
    asm volatile(
        "mma.sync.aligned.m16n8k16.row.col.f32.f16.f16.f32 "
        "{%0,%1,%2,%3}, {%4,%5,%6,%7}, {%8,%9}, {%0,%1,%2,%3};"
        : "+f"(c[0]), "+f"(c[1]), "+f"(c[2]), "+f"(c[3])
        : "r"(a[0]), "r"(a[1]), "r"(a[2]), "r"(a[3]), "r"(b0), "r"(b1));
}

// =================== adj -> fp16 ===========================================
__global__ void tof16_k(const float* __restrict__ in, __half* __restrict__ out)
{
    size_t i = ((size_t)blockIdx.x * blockDim.x + threadIdx.x) * 8;
    float4 a = *(const float4*)(in + i);
    float4 b = *(const float4*)(in + i + 4);
    float v[8] = {a.x, a.y, a.z, a.w, b.x, b.y, b.z, b.w};
    uint32_t H[4];
    #pragma unroll
    for (int k = 0; k < 4; k++) {
        __half h0 = __float2half_rn(v[2*k]);
        __half h1 = __float2half_rn(v[2*k+1]);
        H[k] = (uint32_t)__half_as_ushort(h0) | ((uint32_t)__half_as_ushort(h1) << 16);
    }
    *(uint4*)(out + i) = make_uint4(H[0], H[1], H[2], H[3]);
}

// =================== fp16 mma.sync GEMM ====================================
// FINAL=true : C = relu(A @ BT^T + bias), full K.
// FINAL=false: Cp[z] = partial over K slice z (fp32, no bias/relu); grid.z=2.
// BM=128, BN=128, BK=32; 8 warps as 2Mx4N (warp tile 64x32); 6-stage cp.async.
#define NSTAGE 6
#define STG_B  16384          // A 8KB + BT 8KB
#define MM_DSMEM (NSTAGE * STG_B)

template<bool FINAL>
__global__ void __launch_bounds__(256, 2)
mma_gemm(const __half* __restrict__ A, const __half* __restrict__ BT,
         const float* __restrict__ bias, float* __restrict__ C, int Ncols)
{
    extern __shared__ char smraw[];
    const uint32_t base = s2u(smraw);
    const int tid = threadIdx.x, wid = tid >> 5, lane = tid & 31;
    const int rowBase = blockIdx.y * 128, colBase = blockIdx.x * 128;
    const int wm = (wid & 1) * 64, wn = (wid >> 1) * 32;
    const size_t kbase = FINAL ? 0 : (size_t)blockIdx.z * (NN / 2);
    const int nt = FINAL ? (NN / 32) : (NN / 64);   // k-tiles in this CTA's slice

    const __half* srcA = A  + (size_t)rowBase * NN + kbase;
    const __half* srcB = BT + (size_t)colBase * NN + kbase;

    // 128 rows x 4 chunks (16B) per matrix = 512 chunks; 2 per thread.
    const int c0 = tid * 2, c1 = tid * 2 + 1;
    const int r0 = c0 >> 2, j0 = c0 & 3;
    const int r1 = c1 >> 2, j1 = c1 & 3;
    const uint32_t d0 = swz64((uint32_t)(r0 * 64 + j0 * 16));
    const uint32_t d1 = swz64((uint32_t)(r1 * 64 + j1 * 16));
    const size_t g0 = (size_t)r0 * NN + j0 * 8;
    const size_t g1 = (size_t)r1 * NN + j1 * 8;

    auto load_stage = [&](int s, int t) {
        const uint32_t stb = base + s * STG_B;
        const size_t koff = (size_t)t * 32;
        asm volatile("cp.async.cg.shared.global [%0], [%1], 16;"
                     :: "r"(stb + d0), "l"(srcA + g0 + koff) : "memory");
        asm volatile("cp.async.cg.shared.global [%0], [%1], 16;"
                     :: "r"(stb + d1), "l"(srcA + g1 + koff) : "memory");
        asm volatile("cp.async.cg.shared.global [%0], [%1], 16;"
                     :: "r"(stb + 8192 + d0), "l"(srcB + g0 + koff) : "memory");
        asm volatile("cp.async.cg.shared.global [%0], [%1], 16;"
                     :: "r"(stb + 8192 + d1), "l"(srcB + g1 + koff) : "memory");
    };

    #pragma unroll
    for (int s = 0; s < NSTAGE - 1; s++) {
        load_stage(s, s);
        asm volatile("cp.async.commit_group;" ::: "memory");
    }

    float acc[4][4][4];
    #pragma unroll
    for (int i = 0; i < 4; i++)
        #pragma unroll
        for (int j = 0; j < 4; j++)
            #pragma unroll
            for (int k = 0; k < 4; k++) acc[i][j][k] = 0.f;

    const int lr = lane & 15;
    const int lc = (lane >> 4) * 16;

    for (int t = 0; t < nt; t++) {
        asm volatile("cp.async.wait_group %0;" :: "n"(NSTAGE - 2) : "memory");
        __syncthreads();

        if (t + NSTAGE - 1 < nt) load_stage((t + NSTAGE - 1) % NSTAGE, t + NSTAGE - 1);
        asm volatile("cp.async.commit_group;" ::: "memory");

        const uint32_t stb = base + (t % NSTAGE) * STG_B;
        #pragma unroll
        for (int ks = 0; ks < 2; ks++) {
            uint32_t afr[4][4];
            #pragma unroll
            for (int mt = 0; mt < 4; mt++)
                ldsm4(afr[mt], stb + swz64((uint32_t)((wm + mt * 16 + lr) * 64 + ks * 32 + lc)));
            #pragma unroll
            for (int g = 0; g < 2; g++) {
                uint32_t bh[4];
                const uint32_t so = swz64((uint32_t)((wn + g * 16 + lr) * 64 + ks * 32 + lc));
                ldsm4(bh, stb + 8192 + so);
                #pragma unroll
                for (int mt = 0; mt < 4; mt++)
                    #pragma unroll
                    for (int h = 0; h < 2; h++)
                        mma16816h(acc[mt][g * 2 + h], afr[mt], bh[h], bh[h + 2]);
            }
        }
    }

    // epilogue
    float* Cout = FINAL ? C : (C + (size_t)blockIdx.z * NN * (size_t)Ncols);
    const int r0e = rowBase + wm + (lane >> 2);
    const int cp0 = colBase + wn + (lane & 3) * 2;
    #pragma unroll
    for (int n8 = 0; n8 < 4; n8++) {
        const int col = cp0 + n8 * 8;
        float2 bv = make_float2(0.f, 0.f);
        if (FINAL) bv = *(const float2*)&bias[col];
        #pragma unroll
        for (int mt = 0; mt < 4; mt++) {
            const int row = r0e + mt * 16;
            float2 v0, v1;
            if (FINAL) {
                v0.x = fmaxf(acc[mt][n8][0] + bv.x, 0.f);
                v0.y = fmaxf(acc[mt][n8][1] + bv.y, 0.f);
                v1.x = fmaxf(acc[mt][n8][2] + bv.x, 0.f);
                v1.y = fmaxf(acc[mt][n8][3] + bv.y, 0.f);
            } else {
                v0.x = acc[mt][n8][0]; v0.y = acc[mt][n8][1];
                v1.x = acc[mt][n8][2]; v1.y = acc[mt][n8][3];
            }
            *(float2*)&Cout[(size_t)row * Ncols + col]       = v0;
            *(float2*)&Cout[(size_t)(row + 8) * Ncols + col] = v1;
        }
    }
}

// combine split-K partials: C = relu(p0 + p1 + bias)
__global__ void combine_relu_k(const float* __restrict__ p, const float* __restrict__ bias,
                               float* __restrict__ C, int Ncols)
{
    const size_t i = ((size_t)blockIdx.x * blockDim.x + threadIdx.x) * 4;
    const int col = (int)(i % Ncols);
    float4 a = *(const float4*)(p + i);
    float4 b = *(const float4*)(p + (size_t)NN * Ncols + i);
    float4 bv = *(const float4*)(bias + col);
    float4 v;
    v.x = fmaxf(a.x + b.x + bv.x, 0.f);
    v.y = fmaxf(a.y + b.y + bv.y, 0.f);
    v.z = fmaxf(a.z + b.z + bv.z, 0.f);
    v.w = fmaxf(a.w + b.w + bv.w, 0.f);
    *(float4*)(C + i) = v;
}

// =================== fp32 SIMT GEMM, epilogue -> transposed fp16 ===========
// Computes P = A[M,K] @ B[K,N] (fp32) and writes BT [N, M] fp16 directly.
__global__ void __launch_bounds__(256, 2)
sgemmT_k(const float* __restrict__ A, const float* __restrict__ B,
         __half* __restrict__ BT, int M, int N, int K)
{
    const int BM = 128, BN = 64, BK = 16;
    __shared__ __align__(16) float As[2][BK][BM];
    __shared__ __align__(16) float Bs[2][BK][BN];

    const int tid = threadIdx.x;
    const int tx  = tid & 15;
    const int ty  = tid >> 4;
    const int rowBase = blockIdx.y * BM;
    const int colBase = blockIdx.x * BN;
    const int nt = K / BK;

    const int ar0 = (tid)       >> 2;
    const int ak0 = ((tid)  & 3) * 4;
    const int ar1 = (tid + 256) >> 2;
    const int ak1 = ((tid + 256) & 3) * 4;
    const int br  = tid >> 4;
    const int bc  = (tid & 15) * 4;

    {
        float4 va0 = *(const float4*)&A[(size_t)(rowBase + ar0) * K + ak0];
        float4 va1 = *(const float4*)&A[(size_t)(rowBase + ar1) * K + ak1];
        As[0][ak0 + 0][ar0] = va0.x; As[0][ak0 + 1][ar0] = va0.y;
        As[0][ak0 + 2][ar0] = va0.z; As[0][ak0 + 3][ar0] = va0.w;
        As[0][ak1 + 0][ar1] = va1.x; As[0][ak1 + 1][ar1] = va1.y;
        As[0][ak1 + 2][ar1] = va1.z; As[0][ak1 + 3][ar1] = va1.w;
        float4 vb = *(const float4*)&B[(size_t)br * N + colBase + bc];
        *(float4*)&Bs[0][br][bc] = vb;
    }
    __syncthreads();

    float acc[8][4];
    #pragma unroll
    for (int i = 0; i < 8; i++)
        #pragma unroll
        for (int j = 0; j < 4; j++) acc[i][j] = 0.0f;

    int buf = 0;
    for (int t = 0; t < nt; t++) {
        float4 pa0, pa1, pb;
        if (t + 1 < nt) {
            const int koff = (t + 1) * BK;
            pa0 = *(const float4*)&A[(size_t)(rowBase + ar0) * K + koff + ak0];
            pa1 = *(const float4*)&A[(size_t)(rowBase + ar1) * K + koff + ak1];
            pb  = *(const float4*)&B[(size_t)(koff + br) * N + colBase + bc];
        }
        #pragma unroll
        for (int k = 0; k < BK; k++) {
            float a[8], b[4];
            *(float4*)&a[0] = *(float4*)&As[buf][k][ty * 8];
            *(float4*)&a[4] = *(float4*)&As[buf][k][ty * 8 + 4];
            *(float4*)&b[0] = *(float4*)&Bs[buf][k][tx * 4];
            #pragma unroll
            for (int i = 0; i < 8; i++)
                #pragma unroll
                for (int j = 0; j < 4; j++)
                    acc[i][j] = fmaf(a[i], b[j], acc[i][j]);
        }
        if (t + 1 < nt) {
            const int nb = buf ^ 1;
            As[nb][ak0 + 0][ar0] = pa0.x; As[nb][ak0 + 1][ar0] = pa0.y;
            As[nb][ak0 + 2][ar0] = pa0.z; As[nb][ak0 + 3][ar0] = pa0.w;
            As[nb][ak1 + 0][ar1] = pa1.x; As[nb][ak1 + 1][ar1] = pa1.y;
            As[nb][ak1 + 2][ar1] = pa1.z; As[nb][ak1 + 3][ar1] = pa1.w;
            *(float4*)&Bs[nb][br][bc] = pb;
            buf = nb;
        }
        __syncthreads();
    }

    // Transposed fp16 epilogue: thread owns rows [rowBase+ty*8, +8), cols tx*4..+3.
    #pragma unroll
    for (int j = 0; j < 4; j++) {
        const int col = colBase + tx * 4 + j;
        ushort h8[8];
        #pragma unroll
        for (int i = 0; i < 8; i++)
            h8[i] = __half_as_ushort(__float2half_rn(acc[i][j]));
        const size_t o = (size_t)col * NN + rowBase + ty * 8;
        *(uint4*)(BT + o) = *(const uint4*)h8;
    }
}

// =================== pooling + head ========================================
__global__ void colpart_k(const float* __restrict__ h2, float* __restrict__ part)
{
    const int b = blockIdx.x;
    const int t = threadIdx.x;
    const float* base = h2 + (size_t)b * 64 * NH2;
    float s0 = 0.f, s1 = 0.f;
    #pragma unroll 4
    for (int r = 0; r < 64; r++) {
        s0 += base[r * NH2 + t];
        s1 += base[r * NH2 + t + 256];
    }
    part[b * NH2 + t]       = s0;
    part[b * NH2 + t + 256] = s1;
}

__global__ void head_k(const float* __restrict__ part,
                       const float* __restrict__ sub_fea,
                       const float* __restrict__ fc1W, const float* __restrict__ fc1b,
                       const float* __restrict__ attW, const float* __restrict__ atta,
                       const float* __restrict__ attb, float* __restrict__ out)
{
    __shared__ float z[NZ];
    __shared__ float sc[NHEADS];
    __shared__ float alpha[NHEADS];
    __shared__ float redAll[256][NCLASS];

    const int t = threadIdx.x;

    float s0 = 0.f, s1 = 0.f;
    for (int b = 0; b < 128; b++) {
        s0 += part[b * NH2 + t];
        s1 += part[b * NH2 + t + 256];
    }
    const float selu_s = 1.0507009873554805f;
    const float selu_a = 1.6732632423543772f;
    float m0 = s0 * (1.0f / NN), m1 = s1 * (1.0f / NN);
    z[t]       = (m0 > 0.f) ? selu_s * m0 : selu_s * selu_a * (expf(m0) - 1.f);
    z[t + 256] = (m1 > 0.f) ? selu_s * m1 : selu_s * selu_a * (expf(m1) - 1.f);

    float xe = fc1b[t];
    #pragma unroll 4
    for (int i = 0; i < NFEXT; i++)
        xe = fmaf(sub_fea[i], fc1W[i * NHID + t], xe);
    z[512 + t] = xe;
    __syncthreads();

    const int w = t >> 5, lane = t & 31;
    if (w < NHEADS) {
        float s = 0.f;
        for (int i = lane; i < NZ; i += 32)
            s = fmaf(z[i], atta[w * NZ + i], s);
        #pragma unroll
        for (int o = 16; o > 0; o >>= 1) s += __shfl_xor_sync(0xffffffffu, s, o);
        if (lane == 0) sc[w] = s;
    }
    __syncthreads();
    if (t == 0) {
        float mx = sc[0];
        for (int h = 1; h < NHEADS; h++) mx = fmaxf(mx, sc[h]);
        float den = 0.f;
        for (int h = 0; h < NHEADS; h++) { alpha[h] = expf(sc[h] - mx); den += alpha[h]; }
        float inv = 1.f / den;
        for (int h = 0; h < NHEADS; h++) alpha[h] *= inv;
    }
    __syncthreads();

    float acc[NCLASS];
    #pragma unroll
    for (int o = 0; o < NCLASS; o++) acc[o] = 0.f;
    for (int idx = t; idx < NHEADS * NZ; idx += 256) {
        const int h = idx / NZ;
        const int i = idx - h * NZ;
        const float wz = alpha[h] * z[i];
        const float* wp = attW + (size_t)idx * NCLASS;
        #pragma unroll
        for (int o = 0; o < NCLASS; o++) acc[o] = fmaf(wz, wp[o], acc[o]);
    }
    #pragma unroll
    for (int o = 0; o < NCLASS; o++) redAll[t][o] = acc[o];
    __syncthreads();

    if (t == 0) {
        float v[NCLASS];
        float mx = -1e30f;
        for (int o = 0; o < NCLASS; o++) {
            float s = 0.f;
            for (int i = 0; i < 256; i++) s += redAll[i][o];
            v[o] = s + attb[o];
            mx = fmaxf(mx, v[o]);
        }
        float den = 0.f;
        for (int o = 0; o < NCLASS; o++) den += expf(v[o] - mx);
        float lse = logf(den) + mx;
        for (int o = 0; o < NCLASS; o++) out[o] = v[o] - lse;
    }
}

// ===========================================================================
extern "C" void kernel_launch(void* const* d_in, const int* in_sizes, int n_in,
                              void* d_out, int out_size)
{
    const float* x      = (const float*)d_in[0];
    const float* adj    = (const float*)d_in[1];
    const float* subfea = (const float*)d_in[2];
    const float* gc1W   = (const float*)d_in[3];
    const float* gc1b   = (const float*)d_in[4];
    const float* gc2W   = (const float*)d_in[5];
    const float* gc2b   = (const float*)d_in[6];
    const float* fc1W   = (const float*)d_in[7];
    const float* fc1b   = (const float*)d_in[8];
    const float* attW   = (const float*)d_in[9];
    const float* atta   = (const float*)d_in[10];
    const float* attb   = (const float*)d_in[11];
    float* out = (float*)d_out;

    __half *adjh, *b1T, *b2T;
    float *h1, *p1, *h2, *part;
    cudaGetSymbolAddress((void**)&adjh, g_adj_h);
    cudaGetSymbolAddress((void**)&b1T,  g_b1T);
    cudaGetSymbolAddress((void**)&h1,   g_h1);
    cudaGetSymbolAddress((void**)&p1,   g_p1);
    cudaGetSymbolAddress((void**)&b2T,  g_b2T);
    cudaGetSymbolAddress((void**)&h2,   g_h2);
    cudaGetSymbolAddress((void**)&part, g_part);

    cudaFuncSetAttribute(mma_gemm<true>,  cudaFuncAttributeMaxDynamicSharedMemorySize, MM_DSMEM);
    cudaFuncSetAttribute(mma_gemm<false>, cudaFuncAttributeMaxDynamicSharedMemorySize, MM_DSMEM);

    // adj -> fp16 (64M elems, 8/thread)
    tof16_k<<<(NN * (size_t)NN) / (8 * 256), 256>>>(adj, adjh);

    // xw1 = x @ gc1_W, fused transposed fp16 output
    sgemmT_k<<<dim3(NHID / 64, NN / 128), 256>>>(
        x, gc1W, b1T, NN, NHID, NFEAT);

    // h1 = relu(adj @ xw1 + gc1_b) — split-K x2 (256 CTAs -> 2/SM resident)
    mma_gemm<false><<<dim3(NHID / 128, NN / 128, 2), 256, MM_DSMEM>>>(
        adjh, b1T, nullptr, p1, NHID);
    combine_relu_k<<<(NN * NHID) / (4 * 256), 256>>>(p1, gc1b, h1, NHID);

    // hw2 = h1 @ gc2_W, fused transposed fp16 output
    sgemmT_k<<<dim3(NH2 / 64, NN / 128), 256>>>(
        h1, gc2W, b2T, NN, NH2, NHID);

    // h2 = relu(adj @ hw2 + gc2_b) — single-pass (256 CTAs resident)
    mma_gemm<true><<<dim3(NH2 / 128, NN / 128), 256, MM_DSMEM>>>(
        adjh, b2T, gc2b, h2, NH2);

    // pooling + head
    colpart_k<<<128, 256>>>(h2, part);
    head_k<<<1, 256>>>(part, subfea, fc1W, fc1b, attW, atta, attb, out);
}

// round 16
// speedup vs baseline: 2.1167x; 1.1280x over previous
#include <cuda_runtime.h>
#include <cuda_fp16.h>
#include <math.h>
#include <stdint.h>

// Problem constants
#define NN      8192
#define NFEAT   512
#define NFEXT   128
#define NHID    256
#define NH2     512      // 2*nhid
#define NZ      768      // 3*nhid
#define NCLASS  10
#define NHEADS  8

// ---------------- scratch (device globals; allocation-free) ----------------
__device__ __align__(16) __half g_adj_h[(size_t)NN * NN];   // 128 MB
__device__ __align__(16) __half g_xh[NN * NFEAT];           // 8 MB  x fp16
__device__ __align__(16) __half g_w1T[NHID * NFEAT];        // 256 KB
__device__ __align__(16) __half g_w2T[NH2 * NHID];          // 256 KB
__device__ __align__(16) __half g_b1T[NHID * NN];           // 4 MB  xw1^T fp16
__device__ __align__(16) __half g_h1h[NN * NHID];           // 4 MB  h1 fp16
__device__ __align__(16) float  g_p1[2u * NN * NHID];       // 16 MB split-K partials
__device__ __align__(16) __half g_b2T[NH2 * NN];            // 8 MB  hw2^T fp16
__device__ __align__(16) float  g_h2[NN * NH2];             // 16 MB
__device__ __align__(16) float  g_part[128 * NH2];

// ============================ helpers ======================================
__device__ __forceinline__ uint32_t s2u(const void* p) {
    uint32_t a;
    asm("{ .reg .u64 t; cvta.to.shared.u64 t, %1; cvt.u32.u64 %0, t; }"
        : "=r"(a) : "l"(p));
    return a;
}
__device__ __forceinline__ uint32_t swz64(uint32_t b) { return b ^ ((b >> 3) & 0x30); }

__device__ __forceinline__ void ldsm4(uint32_t* r, uint32_t a) {
    asm volatile("ldmatrix.sync.aligned.m8n8.x4.shared.b16 {%0,%1,%2,%3}, [%4];"
                 : "=r"(r[0]), "=r"(r[1]), "=r"(r[2]), "=r"(r[3]) : "r"(a));
}
__device__ __forceinline__ void mma16816h(float* c, const uint32_t* a,
                                          uint32_t b0, uint32_t b1) {
    asm volatile(
        "mma.sync.aligned.m16n8k16.row.col.f32.f16.f16.f32 "
        "{%0,%1,%2,%3}, {%4,%5,%6,%7}, {%8,%9}, {%0,%1,%2,%3};"
        : "+f"(c[0]), "+f"(c[1]), "+f"(c[2]), "+f"(c[3])
        : "r"(a[0]), "r"(a[1]), "r"(a[2]), "r"(a[3]), "r"(b0), "r"(b1));
}

// =================== fp32 -> fp16 bulk convert =============================
__global__ void tof16_k(const float* __restrict__ in, __half* __restrict__ out)
{
    size_t i = ((size_t)blockIdx.x * blockDim.x + threadIdx.x) * 8;
    float4 a = *(const float4*)(in + i);
    float4 b = *(const float4*)(in + i + 4);
    float v[8] = {a.x, a.y, a.z, a.w, b.x, b.y, b.z, b.w};
    uint32_t H[4];
    #pragma unroll
    for (int k = 0; k < 4; k++) {
        __half h0 = __float2half_rn(v[2*k]);
        __half h1 = __float2half_rn(v[2*k+1]);
        H[k] = (uint32_t)__half_as_ushort(h0) | ((uint32_t)__half_as_ushort(h1) << 16);
    }
    *(uint4*)(out + i) = make_uint4(H[0], H[1], H[2], H[3]);
}

// =================== weight transpose: [R,C] fp32 -> [C,R] fp16 ============
__global__ void transW_k(const float* __restrict__ in, __half* __restrict__ out,
                         int R, int C)
{
    __shared__ float t[32][33];
    const int c0 = blockIdx.x * 32, r0 = blockIdx.y * 32;
    const int tx = threadIdx.x, ty = threadIdx.y;
    #pragma unroll
    for (int k = 0; k < 4; k++)
        t[ty + k * 8][tx] = in[(size_t)(r0 + ty + k * 8) * C + c0 + tx];
    __syncthreads();
    #pragma unroll
    for (int k = 0; k < 4; k++)
        out[(size_t)(c0 + ty + k * 8) * R + r0 + tx] = __float2half_rn(t[tx][ty + k * 8]);
}

// =================== fp16 mma.sync GEMM (big layers) =======================
// FINAL=true : C = relu(A @ BT^T + bias), full K.
// FINAL=false: Cp[z] = partial over K slice z (fp32, no bias/relu); grid.z=2.
// BM=128, BN=128, BK=32; 8 warps as 2Mx4N (warp tile 64x32); 6-stage cp.async.
#define NSTAGE 6
#define STG_B  16384          // A 8KB + BT 8KB
#define MM_DSMEM (NSTAGE * STG_B)

template<bool FINAL>
__global__ void __launch_bounds__(256, 2)
mma_gemm(const __half* __restrict__ A, const __half* __restrict__ BT,
         const float* __restrict__ bias, float* __restrict__ C, int Ncols)
{
    extern __shared__ char smraw[];
    const uint32_t base = s2u(smraw);
    const int tid = threadIdx.x, wid = tid >> 5, lane = tid & 31;
    const int rowBase = blockIdx.y * 128, colBase = blockIdx.x * 128;
    const int wm = (wid & 1) * 64, wn = (wid >> 1) * 32;
    const size_t kbase = FINAL ? 0 : (size_t)blockIdx.z * (NN / 2);
    const int nt = FINAL ? (NN / 32) : (NN / 64);

    const __half* srcA = A  + (size_t)rowBase * NN + kbase;
    const __half* srcB = BT + (size_t)colBase * NN + kbase;

    const int c0 = tid * 2, c1 = tid * 2 + 1;
    const int r0 = c0 >> 2, j0 = c0 & 3;
    const int r1 = c1 >> 2, j1 = c1 & 3;
    const uint32_t d0 = swz64((uint32_t)(r0 * 64 + j0 * 16));
    const uint32_t d1 = swz64((uint32_t)(r1 * 64 + j1 * 16));
    const size_t g0 = (size_t)r0 * NN + j0 * 8;
    const size_t g1 = (size_t)r1 * NN + j1 * 8;

    auto load_stage = [&](int s, int t) {
        const uint32_t stb = base + s * STG_B;
        const size_t koff = (size_t)t * 32;
        asm volatile("cp.async.cg.shared.global [%0], [%1], 16;"
                     :: "r"(stb + d0), "l"(srcA + g0 + koff) : "memory");
        asm volatile("cp.async.cg.shared.global [%0], [%1], 16;"
                     :: "r"(stb + d1), "l"(srcA + g1 + koff) : "memory");
        asm volatile("cp.async.cg.shared.global [%0], [%1], 16;"
                     :: "r"(stb + 8192 + d0), "l"(srcB + g0 + koff) : "memory");
        asm volatile("cp.async.cg.shared.global [%0], [%1], 16;"
                     :: "r"(stb + 8192 + d1), "l"(srcB + g1 + koff) : "memory");
    };

    #pragma unroll
    for (int s = 0; s < NSTAGE - 1; s++) {
        load_stage(s, s);
        asm volatile("cp.async.commit_group;" ::: "memory");
    }

    float acc[4][4][4];
    #pragma unroll
    for (int i = 0; i < 4; i++)
        #pragma unroll
        for (int j = 0; j < 4; j++)
            #pragma unroll
            for (int k = 0; k < 4; k++) acc[i][j][k] = 0.f;

    const int lr = lane & 15;
    const int lc = (lane >> 4) * 16;

    for (int t = 0; t < nt; t++) {
        asm volatile("cp.async.wait_group %0;" :: "n"(NSTAGE - 2) : "memory");
        __syncthreads();

        if (t + NSTAGE - 1 < nt) load_stage((t + NSTAGE - 1) % NSTAGE, t + NSTAGE - 1);
        asm volatile("cp.async.commit_group;" ::: "memory");

        const uint32_t stb = base + (t % NSTAGE) * STG_B;
        #pragma unroll
        for (int ks = 0; ks < 2; ks++) {
            uint32_t afr[4][4];
            #pragma unroll
            for (int mt = 0; mt < 4; mt++)
                ldsm4(afr[mt], stb + swz64((uint32_t)((wm + mt * 16 + lr) * 64 + ks * 32 + lc)));
            #pragma unroll
            for (int g = 0; g < 2; g++) {
                uint32_t bh[4];
                const uint32_t so = swz64((uint32_t)((wn + g * 16 + lr) * 64 + ks * 32 + lc));
                ldsm4(bh, stb + 8192 + so);
                #pragma unroll
                for (int mt = 0; mt < 4; mt++)
                    #pragma unroll
                    for (int h = 0; h < 2; h++)
                        mma16816h(acc[mt][g * 2 + h], afr[mt], bh[h], bh[h + 2]);
            }
        }
    }

    float* Cout = FINAL ? C : (C + (size_t)blockIdx.z * NN * (size_t)Ncols);
    const int r0e = rowBase + wm + (lane >> 2);
    const int cp0 = colBase + wn + (lane & 3) * 2;
    #pragma unroll
    for (int n8 = 0; n8 < 4; n8++) {
        const int col = cp0 + n8 * 8;
        float2 bv = make_float2(0.f, 0.f);
        if (FINAL) bv = *(const float2*)&bias[col];
        #pragma unroll
        for (int mt = 0; mt < 4; mt++) {
            const int row = r0e + mt * 16;
            float2 v0, v1;
            if (FINAL) {
                v0.x = fmaxf(acc[mt][n8][0] + bv.x, 0.f);
                v0.y = fmaxf(acc[mt][n8][1] + bv.y, 0.f);
                v1.x = fmaxf(acc[mt][n8][2] + bv.x, 0.f);
                v1.y = fmaxf(acc[mt][n8][3] + bv.y, 0.f);
            } else {
                v0.x = acc[mt][n8][0]; v0.y = acc[mt][n8][1];
                v1.x = acc[mt][n8][2]; v1.y = acc[mt][n8][3];
            }
            *(float2*)&Cout[(size_t)row * Ncols + col]       = v0;
            *(float2*)&Cout[(size_t)(row + 8) * Ncols + col] = v1;
        }
    }
}

// =================== fp16 mma B-generator ==================================
// BT[M, 8192] (fp16) = WT[M, K] @ Bsrc[8192, K]^T   (both fp16, K-contiguous)
// Output row m = column m of (Bsrc @ W); exactly the BT layout mma_gemm wants.
// Same tile scheme as mma_gemm; row stride = K (runtime).
__global__ void __launch_bounds__(256, 2)
mma_bgen(const __half* __restrict__ WT, const __half* __restrict__ Bsrc,
         __half* __restrict__ BT, int K)
{
    extern __shared__ char smraw[];
    const uint32_t base = s2u(smraw);
    const int tid = threadIdx.x, wid = tid >> 5, lane = tid & 31;
    const int rowBase = blockIdx.y * 128, colBase = blockIdx.x * 128;
    const int wm = (wid & 1) * 64, wn = (wid >> 1) * 32;
    const int nt = K / 32;

    const __half* srcA = WT   + (size_t)rowBase * K;
    const __half* srcB = Bsrc + (size_t)colBase * K;

    const int c0 = tid * 2, c1 = tid * 2 + 1;
    const int r0 = c0 >> 2, j0 = c0 & 3;
    const int r1 = c1 >> 2, j1 = c1 & 3;
    const uint32_t d0 = swz64((uint32_t)(r0 * 64 + j0 * 16));
    const uint32_t d1 = swz64((uint32_t)(r1 * 64 + j1 * 16));
    const size_t g0 = (size_t)r0 * K + j0 * 8;
    const size_t g1 = (size_t)r1 * K + j1 * 8;

    auto load_stage = [&](int s, int t) {
        const uint32_t stb = base + s * STG_B;
        const size_t koff = (size_t)t * 32;
        asm volatile("cp.async.cg.shared.global [%0], [%1], 16;"
                     :: "r"(stb + d0), "l"(srcA + g0 + koff) : "memory");
        asm volatile("cp.async.cg.shared.global [%0], [%1], 16;"
                     :: "r"(stb + d1), "l"(srcA + g1 + koff) : "memory");
        asm volatile("cp.async.cg.shared.global [%0], [%1], 16;"
                     :: "r"(stb + 8192 + d0), "l"(srcB + g0 + koff) : "memory");
        asm volatile("cp.async.cg.shared.global [%0], [%1], 16;"
                     :: "r"(stb + 8192 + d1), "l"(srcB + g1 + koff) : "memory");
    };

    const int npre = (NSTAGE - 1 < nt) ? NSTAGE - 1 : nt;
    for (int s = 0; s < npre; s++) {
        load_stage(s, s);
        asm volatile("cp.async.commit_group;" ::: "memory");
    }
    for (int s = npre; s < NSTAGE - 1; s++)
        asm volatile("cp.async.commit_group;" ::: "memory");

    float acc[4][4][4];
    #pragma unroll
    for (int i = 0; i < 4; i++)
        #pragma unroll
        for (int j = 0; j < 4; j++)
            #pragma unroll
            for (int k = 0; k < 4; k++) acc[i][j][k] = 0.f;

    const int lr = lane & 15;
    const int lc = (lane >> 4) * 16;

    for (int t = 0; t < nt; t++) {
        asm volatile("cp.async.wait_group %0;" :: "n"(NSTAGE - 2) : "memory");
        __syncthreads();

        if (t + NSTAGE - 1 < nt) load_stage((t + NSTAGE - 1) % NSTAGE, t + NSTAGE - 1);
        asm volatile("cp.async.commit_group;" ::: "memory");

        const uint32_t stb = base + (t % NSTAGE) * STG_B;
        #pragma unroll
        for (int ks = 0; ks < 2; ks++) {
            uint32_t afr[4][4];
            #pragma unroll
            for (int mt = 0; mt < 4; mt++)
                ldsm4(afr[mt], stb + swz64((uint32_t)((wm + mt * 16 + lr) * 64 + ks * 32 + lc)));
            #pragma unroll
            for (int g = 0; g < 2; g++) {
                uint32_t bh[4];
                const uint32_t so = swz64((uint32_t)((wn + g * 16 + lr) * 64 + ks * 32 + lc));
                ldsm4(bh, stb + 8192 + so);
                #pragma unroll
                for (int mt = 0; mt < 4; mt++)
                    #pragma unroll
                    for (int h = 0; h < 2; h++)
                        mma16816h(acc[mt][g * 2 + h], afr[mt], bh[h], bh[h + 2]);
            }
        }
    }

    const int r0e = rowBase + wm + (lane >> 2);
    const int cp0 = colBase + wn + (lane & 3) * 2;
    #pragma unroll
    for (int n8 = 0; n8 < 4; n8++) {
        const int col = cp0 + n8 * 8;
        #pragma unroll
        for (int mt = 0; mt < 4; mt++) {
            const int row = r0e + mt * 16;
            __half2 h0 = __floats2half2_rn(acc[mt][n8][0], acc[mt][n8][1]);
            __half2 h1 = __floats2half2_rn(acc[mt][n8][2], acc[mt][n8][3]);
            *(__half2*)&BT[(size_t)row * NN + col]       = h0;
            *(__half2*)&BT[(size_t)(row + 8) * NN + col] = h1;
        }
    }
}

// combine split-K partials: h1 = relu(p0 + p1 + bias) -> fp16 row-major
__global__ void combine_relu_h(const float* __restrict__ p, const float* __restrict__ bias,
                               __half* __restrict__ C, int Ncols)
{
    const size_t i = ((size_t)blockIdx.x * blockDim.x + threadIdx.x) * 4;
    const int col = (int)(i % Ncols);
    float4 a = *(const float4*)(p + i);
    float4 b = *(const float4*)(p + (size_t)NN * Ncols + i);
    float4 bv = *(const float4*)(bias + col);
    __half2 h0 = __floats2half2_rn(fmaxf(a.x + b.x + bv.x, 0.f),
                                   fmaxf(a.y + b.y + bv.y, 0.f));
    __half2 h1 = __floats2half2_rn(fmaxf(a.z + b.z + bv.z, 0.f),
                                   fmaxf(a.w + b.w + bv.w, 0.f));
    *(__half2*)&C[i]     = h0;
    *(__half2*)&C[i + 2] = h1;
}

// =================== pooling + head ========================================
__global__ void colpart_k(const float* __restrict__ h2, float* __restrict__ part)
{
    const int b = blockIdx.x;
    const int t = threadIdx.x;
    const float* base = h2 + (size_t)b * 64 * NH2;
    float s0 = 0.f, s1 = 0.f;
    #pragma unroll 4
    for (int r = 0; r < 64; r++) {
        s0 += base[r * NH2 + t];
        s1 += base[r * NH2 + t + 256];
    }
    part[b * NH2 + t]       = s0;
    part[b * NH2 + t + 256] = s1;
}

__global__ void head_k(const float* __restrict__ part,
                       const float* __restrict__ sub_fea,
                       const float* __restrict__ fc1W, const float* __restrict__ fc1b,
                       const float* __restrict__ attW, const float* __restrict__ atta,
                       const float* __restrict__ attb, float* __restrict__ out)
{
    __shared__ float z[NZ];
    __shared__ float sc[NHEADS];
    __shared__ float alpha[NHEADS];
    __shared__ float redAll[256][NCLASS];

    const int t = threadIdx.x;

    float s0 = 0.f, s1 = 0.f;
    for (int b = 0; b < 128; b++) {
        s0 += part[b * NH2 + t];
        s1 += part[b * NH2 + t + 256];
    }
    const float selu_s = 1.0507009873554805f;
    const float selu_a = 1.6732632423543772f;
    float m0 = s0 * (1.0f / NN), m1 = s1 * (1.0f / NN);
    z[t]       = (m0 > 0.f) ? selu_s * m0 : selu_s * selu_a * (expf(m0) - 1.f);
    z[t + 256] = (m1 > 0.f) ? selu_s * m1 : selu_s * selu_a * (expf(m1) - 1.f);

    float xe = fc1b[t];
    #pragma unroll 4
    for (int i = 0; i < NFEXT; i++)
        xe = fmaf(sub_fea[i], fc1W[i * NHID + t], xe);
    z[512 + t] = xe;
    __syncthreads();

    const int w = t >> 5, lane = t & 31;
    if (w < NHEADS) {
        float s = 0.f;
        for (int i = lane; i < NZ; i += 32)
            s = fmaf(z[i], atta[w * NZ + i], s);
        #pragma unroll
        for (int o = 16; o > 0; o >>= 1) s += __shfl_xor_sync(0xffffffffu, s, o);
        if (lane == 0) sc[w] = s;
    }
    __syncthreads();
    if (t == 0) {
        float mx = sc[0];
        for (int h = 1; h < NHEADS; h++) mx = fmaxf(mx, sc[h]);
        float den = 0.f;
        for (int h = 0; h < NHEADS; h++) { alpha[h] = expf(sc[h] - mx); den += alpha[h]; }
        float inv = 1.f / den;
        for (int h = 0; h < NHEADS; h++) alpha[h] *= inv;
    }
    __syncthreads();

    float acc[NCLASS];
    #pragma unroll
    for (int o = 0; o < NCLASS; o++) acc[o] = 0.f;
    for (int idx = t; idx < NHEADS * NZ; idx += 256) {
        const int h = idx / NZ;
        const int i = idx - h * NZ;
        const float wz = alpha[h] * z[i];
        const float* wp = attW + (size_t)idx * NCLASS;
        #pragma unroll
        for (int o = 0; o < NCLASS; o++) acc[o] = fmaf(wz, wp[o], acc[o]);
    }
    #pragma unroll
    for (int o = 0; o < NCLASS; o++) redAll[t][o] = acc[o];
    __syncthreads();

    if (t == 0) {
        float v[NCLASS];
        float mx = -1e30f;
        for (int o = 0; o < NCLASS; o++) {
            float s = 0.f;
            for (int i = 0; i < 256; i++) s += redAll[i][o];
            v[o] = s + attb[o];
            mx = fmaxf(mx, v[o]);
        }
        float den = 0.f;
        for (int o = 0; o < NCLASS; o++) den += expf(v[o] - mx);
        float lse = logf(den) + mx;
        for (int o = 0; o < NCLASS; o++) out[o] = v[o] - lse;
    }
}

// ===========================================================================
extern "C" void kernel_launch(void* const* d_in, const int* in_sizes, int n_in,
                              void* d_out, int out_size)
{
    const float* x      = (const float*)d_in[0];
    const float* adj    = (const float*)d_in[1];
    const float* subfea = (const float*)d_in[2];
    const float* gc1W   = (const float*)d_in[3];
    const float* gc1b   = (const float*)d_in[4];
    const float* gc2W   = (const float*)d_in[5];
    const float* gc2b   = (const float*)d_in[6];
    const float* fc1W   = (const float*)d_in[7];
    const float* fc1b   = (const float*)d_in[8];
    const float* attW   = (const float*)d_in[9];
    const float* atta   = (const float*)d_in[10];
    const float* attb   = (const float*)d_in[11];
    float* out = (float*)d_out;

    __half *adjh, *xh, *w1T, *w2T, *b1T, *h1h, *b2T;
    float *p1, *h2, *part;
    cudaGetSymbolAddress((void**)&adjh, g_adj_h);
    cudaGetSymbolAddress((void**)&xh,   g_xh);
    cudaGetSymbolAddress((void**)&w1T,  g_w1T);
    cudaGetSymbolAddress((void**)&w2T,  g_w2T);
    cudaGetSymbolAddress((void**)&b1T,  g_b1T);
    cudaGetSymbolAddress((void**)&h1h,  g_h1h);
    cudaGetSymbolAddress((void**)&p1,   g_p1);
    cudaGetSymbolAddress((void**)&b2T,  g_b2T);
    cudaGetSymbolAddress((void**)&h2,   g_h2);
    cudaGetSymbolAddress((void**)&part, g_part);

    cudaFuncSetAttribute(mma_gemm<true>,  cudaFuncAttributeMaxDynamicSharedMemorySize, MM_DSMEM);
    cudaFuncSetAttribute(mma_gemm<false>, cudaFuncAttributeMaxDynamicSharedMemorySize, MM_DSMEM);
    cudaFuncSetAttribute(mma_bgen,        cudaFuncAttributeMaxDynamicSharedMemorySize, MM_DSMEM);

    // converts: adj and x -> fp16
    tof16_k<<<(NN * (size_t)NN) / (8 * 256), 256>>>(adj, adjh);
    tof16_k<<<(NN * (size_t)NFEAT) / (8 * 256), 256>>>(x, xh);

    // W1 [512,256] -> W1T [256,512] fp16;  W2 [256,512] -> W2T [512,256] fp16
    transW_k<<<dim3(NHID / 32, NFEAT / 32), dim3(32, 8)>>>(gc1W, w1T, NFEAT, NHID);
    transW_k<<<dim3(NH2 / 32, NHID / 32), dim3(32, 8)>>>(gc2W, w2T, NHID, NH2);

    // b1T[256,8192] = W1T @ x^T  (tensor; output IS the BT layout)
    mma_bgen<<<dim3(NN / 128, NHID / 128), 256, MM_DSMEM>>>(w1T, xh, b1T, NFEAT);

    // h1 = relu(adj @ xw1 + gc1_b) — split-K x2; combine emits fp16 row-major
    mma_gemm<false><<<dim3(NHID / 128, NN / 128, 2), 256, MM_DSMEM>>>(
        adjh, b1T, nullptr, p1, NHID);
    combine_relu_h<<<(NN * NHID) / (4 * 256), 256>>>(p1, gc1b, h1h, NHID);

    // b2T[512,8192] = W2T @ h1^T  (tensor)
    mma_bgen<<<dim3(NN / 128, NH2 / 128), 256, MM_DSMEM>>>(w2T, h1h, b2T, NHID);

    // h2 = relu(adj @ hw2 + gc2_b)
    mma_gemm<true><<<dim3(NH2 / 128, NN / 128), 256, MM_DSMEM>>>(
        adjh, b2T, gc2b, h2, NH2);

    // pooling + head
    colpart_k<<<128, 256>>>(h2, part);
    head_k<<<1, 256>>>(part, subfea, fc1W, fc1b, attW, atta, attb, out);
}

// round 17
// speedup vs baseline: 2.2019x; 1.0402x over previous
#include <cuda_runtime.h>
#include <cuda_fp16.h>
#include <cuda_fp8.h>
#include <math.h>
#include <stdint.h>

// Problem constants
#define NN      8192
#define NFEAT   512
#define NFEXT   128
#define NHID    256
#define NH2     512      // 2*nhid
#define NZ      768      // 3*nhid
#define NCLASS  10
#define NHEADS  8

#define ADJ_SCALE   8192.0f
#define B2_SCALE    256.0f

// ---------------- scratch (device globals; allocation-free) ----------------
__device__ __align__(16) uint8_t g_adj8[(size_t)NN * NN];   // 64 MB adj e4m3 (x8192)
__device__ __align__(16) __half  g_xh[NN * NFEAT];          // 8 MB  x fp16
__device__ __align__(16) __half  g_w1T[NHID * NFEAT];       // 256 KB
__device__ __align__(16) __half  g_w2T[NH2 * NHID];         // 256 KB
__device__ __align__(16) uint8_t g_b1T[(size_t)NHID * NN];  // 2 MB  xw1^T e4m3
__device__ __align__(16) __half  g_h1h[NN * NHID];          // 4 MB  h1 fp16
__device__ __align__(16) float   g_p1[2u * NN * NHID];      // 16 MB split-K partials
__device__ __align__(16) uint8_t g_b2T[(size_t)NH2 * NN];   // 4 MB  hw2^T e4m3 (x256)
__device__ __align__(16) float   g_h2[NN * NH2];            // 16 MB
__device__ __align__(16) float   g_part[128 * NH2];

// ============================ helpers ======================================
__device__ __forceinline__ uint32_t s2u(const void* p) {
    uint32_t a;
    asm("{ .reg .u64 t; cvta.to.shared.u64 t, %1; cvt.u32.u64 %0, t; }"
        : "=r"(a) : "l"(p));
    return a;
}
__device__ __forceinline__ uint32_t swz64(uint32_t b) { return b ^ ((b >> 3) & 0x30); }

__device__ __forceinline__ void ldsm4(uint32_t* r, uint32_t a) {
    asm volatile("ldmatrix.sync.aligned.m8n8.x4.shared.b16 {%0,%1,%2,%3}, [%4];"
                 : "=r"(r[0]), "=r"(r[1]), "=r"(r[2]), "=r"(r[3]) : "r"(a));
}
__device__ __forceinline__ void mma16816h(float* c, const uint32_t* a,
                                          uint32_t b0, uint32_t b1) {
    asm volatile(
        "mma.sync.aligned.m16n8k16.row.col.f32.f16.f16.f32 "
        "{%0,%1,%2,%3}, {%4,%5,%6,%7}, {%8,%9}, {%0,%1,%2,%3};"
        : "+f"(c[0]), "+f"(c[1]), "+f"(c[2]), "+f"(c[3])
        : "r"(a[0]), "r"(a[1]), "r"(a[2]), "r"(a[3]), "r"(b0), "r"(b1));
}
// fp8 e4m3: byte-level fragment layout identical to fp16 k16 (32B per A-row)
__device__ __forceinline__ void mma16832f8(float* c, const uint32_t* a,
                                           uint32_t b0, uint32_t b1) {
    asm volatile(
        "mma.sync.aligned.m16n8k32.row.col.f32.e4m3.e4m3.f32 "
        "{%0,%1,%2,%3}, {%4,%5,%6,%7}, {%8,%9}, {%0,%1,%2,%3};"
        : "+f"(c[0]), "+f"(c[1]), "+f"(c[2]), "+f"(c[3])
        : "r"(a[0]), "r"(a[1]), "r"(a[2]), "r"(a[3]), "r"(b0), "r"(b1));
}

// =================== adj fp32 -> e4m3 (x8192) ==============================
__global__ void tof8_k(const float* __restrict__ in, uint8_t* __restrict__ out)
{
    size_t i = ((size_t)blockIdx.x * blockDim.x + threadIdx.x) * 8;
    float4 a = *(const float4*)(in + i);
    float4 b = *(const float4*)(in + i + 4);
    float v[8] = {a.x, a.y, a.z, a.w, b.x, b.y, b.z, b.w};
    uint8_t o[8];
    #pragma unroll
    for (int k = 0; k < 8; k++)
        o[k] = (uint8_t)__nv_cvt_float_to_fp8(v[k] * ADJ_SCALE, __NV_SATFINITE, __NV_E4M3);
    *(uint2*)(out + i) = *(const uint2*)o;
}

// =================== fp32 -> fp16 bulk convert =============================
__global__ void tof16_k(const float* __restrict__ in, __half* __restrict__ out)
{
    size_t i = ((size_t)blockIdx.x * blockDim.x + threadIdx.x) * 8;
    float4 a = *(const float4*)(in + i);
    float4 b = *(const float4*)(in + i + 4);
    float v[8] = {a.x, a.y, a.z, a.w, b.x, b.y, b.z, b.w};
    uint32_t H[4];
    #pragma unroll
    for (int k = 0; k < 4; k++) {
        __half h0 = __float2half_rn(v[2*k]);
        __half h1 = __float2half_rn(v[2*k+1]);
        H[k] = (uint32_t)__half_as_ushort(h0) | ((uint32_t)__half_as_ushort(h1) << 16);
    }
    *(uint4*)(out + i) = make_uint4(H[0], H[1], H[2], H[3]);
}

// =================== weight transpose: [R,C] fp32 -> [C,R] fp16 ============
__global__ void transW_k(const float* __restrict__ in, __half* __restrict__ out,
                         int R, int C)
{
    __shared__ float t[32][33];
    const int c0 = blockIdx.x * 32, r0 = blockIdx.y * 32;
    const int tx = threadIdx.x, ty = threadIdx.y;
    #pragma unroll
    for (int k = 0; k < 4; k++)
        t[ty + k * 8][tx] = in[(size_t)(r0 + ty + k * 8) * C + c0 + tx];
    __syncthreads();
    #pragma unroll
    for (int k = 0; k < 4; k++)
        out[(size_t)(c0 + ty + k * 8) * R + r0 + tx] = __float2half_rn(t[tx][ty + k * 8]);
}

// =================== e4m3 mma.sync GEMM (big layers) =======================
// FINAL=true : C = relu(invscale * (A8 @ BT8^T) + bias), full K.
// FINAL=false: Cp[z] = invscale * partial over K slice z; grid.z=2.
// Byte-tiles: 128 rows x 64 bytes per matrix per stage (same as fp16 version;
// 64 bytes now = 64 fp8 k-values so k-tile count halves). 6-stage cp.async.
#define NSTAGE 6
#define STG_B  16384          // A 8KB + BT 8KB
#define MM_DSMEM (NSTAGE * STG_B)

template<bool FINAL>
__global__ void __launch_bounds__(256, 2)
mma_gemm8(const uint8_t* __restrict__ A, const uint8_t* __restrict__ BT,
          const float* __restrict__ bias, float* __restrict__ C, int Ncols,
          float invscale)
{
    extern __shared__ char smraw[];
    const uint32_t base = s2u(smraw);
    const int tid = threadIdx.x, wid = tid >> 5, lane = tid & 31;
    const int rowBase = blockIdx.y * 128, colBase = blockIdx.x * 128;
    const int wm = (wid & 1) * 64, wn = (wid >> 1) * 32;
    const size_t kbase = FINAL ? 0 : (size_t)blockIdx.z * (NN / 2);  // bytes
    const int nt = FINAL ? (NN / 64) : (NN / 128);   // 64-byte k-tiles

    const uint8_t* srcA = A  + (size_t)rowBase * NN + kbase;
    const uint8_t* srcB = BT + (size_t)colBase * NN + kbase;

    // 128 rows x 4 chunks (16B) per matrix = 512 chunks; 2 per thread.
    const int c0 = tid * 2, c1 = tid * 2 + 1;
    const int r0 = c0 >> 2, j0 = c0 & 3;
    const int r1 = c1 >> 2, j1 = c1 & 3;
    const uint32_t d0 = swz64((uint32_t)(r0 * 64 + j0 * 16));
    const uint32_t d1 = swz64((uint32_t)(r1 * 64 + j1 * 16));
    const size_t g0 = (size_t)r0 * NN + j0 * 16;
    const size_t g1 = (size_t)r1 * NN + j1 * 16;

    auto load_stage = [&](int s, int t) {
        const uint32_t stb = base + s * STG_B;
        const size_t koff = (size_t)t * 64;
        asm volatile("cp.async.cg.shared.global [%0], [%1], 16;"
                     :: "r"(stb + d0), "l"(srcA + g0 + koff) : "memory");
        asm volatile("cp.async.cg.shared.global [%0], [%1], 16;"
                     :: "r"(stb + d1), "l"(srcA + g1 + koff) : "memory");
        asm volatile("cp.async.cg.shared.global [%0], [%1], 16;"
                     :: "r"(stb + 8192 + d0), "l"(srcB + g0 + koff) : "memory");
        asm volatile("cp.async.cg.shared.global [%0], [%1], 16;"
                     :: "r"(stb + 8192 + d1), "l"(srcB + g1 + koff) : "memory");
    };

    #pragma unroll
    for (int s = 0; s < NSTAGE - 1; s++) {
        load_stage(s, s);
        asm volatile("cp.async.commit_group;" ::: "memory");
    }

    float acc[4][4][4];
    #pragma unroll
    for (int i = 0; i < 4; i++)
        #pragma unroll
        for (int j = 0; j < 4; j++)
            #pragma unroll
            for (int k = 0; k < 4; k++) acc[i][j][k] = 0.f;

    const int lr = lane & 15;
    const int lc = (lane >> 4) * 16;

    for (int t = 0; t < nt; t++) {
        asm volatile("cp.async.wait_group %0;" :: "n"(NSTAGE - 2) : "memory");
        __syncthreads();

        if (t + NSTAGE - 1 < nt) load_stage((t + NSTAGE - 1) % NSTAGE, t + NSTAGE - 1);
        asm volatile("cp.async.commit_group;" ::: "memory");

        const uint32_t stb = base + (t % NSTAGE) * STG_B;
        #pragma unroll
        for (int ks = 0; ks < 2; ks++) {      // 2 x k32 per 64-byte tile
            uint32_t afr[4][4];
            #pragma unroll
            for (int mt = 0; mt < 4; mt++)
                ldsm4(afr[mt], stb + swz64((uint32_t)((wm + mt * 16 + lr) * 64 + ks * 32 + lc)));
            #pragma unroll
            for (int g = 0; g < 2; g++) {
                uint32_t bh[4];
                const uint32_t so = swz64((uint32_t)((wn + g * 16 + lr) * 64 + ks * 32 + lc));
                ldsm4(bh, stb + 8192 + so);
                #pragma unroll
                for (int mt = 0; mt < 4; mt++)
                    #pragma unroll
                    for (int h = 0; h < 2; h++)
                        mma16832f8(acc[mt][g * 2 + h], afr[mt], bh[h], bh[h + 2]);
            }
        }
    }

    float* Cout = FINAL ? C : (C + (size_t)blockIdx.z * NN * (size_t)Ncols);
    const int r0e = rowBase + wm + (lane >> 2);
    const int cp0 = colBase + wn + (lane & 3) * 2;
    #pragma unroll
    for (int n8 = 0; n8 < 4; n8++) {
        const int col = cp0 + n8 * 8;
        float2 bv = make_float2(0.f, 0.f);
        if (FINAL) bv = *(const float2*)&bias[col];
        #pragma unroll
        for (int mt = 0; mt < 4; mt++) {
            const int row = r0e + mt * 16;
            float2 v0, v1;
            if (FINAL) {
                v0.x = fmaxf(fmaf(acc[mt][n8][0], invscale, bv.x), 0.f);
                v0.y = fmaxf(fmaf(acc[mt][n8][1], invscale, bv.y), 0.f);
                v1.x = fmaxf(fmaf(acc[mt][n8][2], invscale, bv.x), 0.f);
                v1.y = fmaxf(fmaf(acc[mt][n8][3], invscale, bv.y), 0.f);
            } else {
                v0.x = acc[mt][n8][0] * invscale; v0.y = acc[mt][n8][1] * invscale;
                v1.x = acc[mt][n8][2] * invscale; v1.y = acc[mt][n8][3] * invscale;
            }
            *(float2*)&Cout[(size_t)row * Ncols + col]       = v0;
            *(float2*)&Cout[(size_t)(row + 8) * Ncols + col] = v1;
        }
    }
}

// =================== fp16 mma B-generator -> e4m3 output ===================
// BT8[M, 8192] (e4m3, x outscale) = WT[M, K] @ Bsrc[8192, K]^T  (fp16 inputs)
__global__ void __launch_bounds__(256, 2)
mma_bgen(const __half* __restrict__ WT, const __half* __restrict__ Bsrc,
         uint8_t* __restrict__ BT, int K, float outscale)
{
    extern __shared__ char smraw[];
    const uint32_t base = s2u(smraw);
    const int tid = threadIdx.x, wid = tid >> 5, lane = tid & 31;
    const int rowBase = blockIdx.y * 128, colBase = blockIdx.x * 128;
    const int wm = (wid & 1) * 64, wn = (wid >> 1) * 32;
    const int nt = K / 32;

    const __half* srcA = WT   + (size_t)rowBase * K;
    const __half* srcB = Bsrc + (size_t)colBase * K;

    const int c0 = tid * 2, c1 = tid * 2 + 1;
    const int r0 = c0 >> 2, j0 = c0 & 3;
    const int r1 = c1 >> 2, j1 = c1 & 3;
    const uint32_t d0 = swz64((uint32_t)(r0 * 64 + j0 * 16));
    const uint32_t d1 = swz64((uint32_t)(r1 * 64 + j1 * 16));
    const size_t g0 = (size_t)r0 * K + j0 * 8;
    const size_t g1 = (size_t)r1 * K + j1 * 8;

    auto load_stage = [&](int s, int t) {
        const uint32_t stb = base + s * STG_B;
        const size_t koff = (size_t)t * 32;
        asm volatile("cp.async.cg.shared.global [%0], [%1], 16;"
                     :: "r"(stb + d0), "l"(srcA + g0 + koff) : "memory");
        asm volatile("cp.async.cg.shared.global [%0], [%1], 16;"
                     :: "r"(stb + d1), "l"(srcA + g1 + koff) : "memory");
        asm volatile("cp.async.cg.shared.global [%0], [%1], 16;"
                     :: "r"(stb + 8192 + d0), "l"(srcB + g0 + koff) : "memory");
        asm volatile("cp.async.cg.shared.global [%0], [%1], 16;"
                     :: "r"(stb + 8192 + d1), "l"(srcB + g1 + koff) : "memory");
    };

    const int npre = (NSTAGE - 1 < nt) ? NSTAGE - 1 : nt;
    for (int s = 0; s < npre; s++) {
        load_stage(s, s);
        asm volatile("cp.async.commit_group;" ::: "memory");
    }
    for (int s = npre; s < NSTAGE - 1; s++)
        asm volatile("cp.async.commit_group;" ::: "memory");

    float acc[4][4][4];
    #pragma unroll
    for (int i = 0; i < 4; i++)
        #pragma unroll
        for (int j = 0; j < 4; j++)
            #pragma unroll
            for (int k = 0; k < 4; k++) acc[i][j][k] = 0.f;

    const int lr = lane & 15;
    const int lc = (lane >> 4) * 16;

    for (int t = 0; t < nt; t++) {
        asm volatile("cp.async.wait_group %0;" :: "n"(NSTAGE - 2) : "memory");
        __syncthreads();

        if (t + NSTAGE - 1 < nt) load_stage((t + NSTAGE - 1) % NSTAGE, t + NSTAGE - 1);
        asm volatile("cp.async.commit_group;" ::: "memory");

        const uint32_t stb = base + (t % NSTAGE) * STG_B;
        #pragma unroll
        for (int ks = 0; ks < 2; ks++) {
            uint32_t afr[4][4];
            #pragma unroll
            for (int mt = 0; mt < 4; mt++)
                ldsm4(afr[mt], stb + swz64((uint32_t)((wm + mt * 16 + lr) * 64 + ks * 32 + lc)));
            #pragma unroll
            for (int g = 0; g < 2; g++) {
                uint32_t bh[4];
                const uint32_t so = swz64((uint32_t)((wn + g * 16 + lr) * 64 + ks * 32 + lc));
                ldsm4(bh, stb + 8192 + so);
                #pragma unroll
                for (int mt = 0; mt < 4; mt++)
                    #pragma unroll
                    for (int h = 0; h < 2; h++)
                        mma16816h(acc[mt][g * 2 + h], afr[mt], bh[h], bh[h + 2]);
            }
        }
    }

    const int r0e = rowBase + wm + (lane >> 2);
    const int cp0 = colBase + wn + (lane & 3) * 2;
    #pragma unroll
    for (int n8 = 0; n8 < 4; n8++) {
        const int col = cp0 + n8 * 8;
        #pragma unroll
        for (int mt = 0; mt < 4; mt++) {
            const int row = r0e + mt * 16;
            uint8_t q00 = (uint8_t)__nv_cvt_float_to_fp8(acc[mt][n8][0] * outscale, __NV_SATFINITE, __NV_E4M3);
            uint8_t q01 = (uint8_t)__nv_cvt_float_to_fp8(acc[mt][n8][1] * outscale, __NV_SATFINITE, __NV_E4M3);
            uint8_t q10 = (uint8_t)__nv_cvt_float_to_fp8(acc[mt][n8][2] * outscale, __NV_SATFINITE, __NV_E4M3);
            uint8_t q11 = (uint8_t)__nv_cvt_float_to_fp8(acc[mt][n8][3] * outscale, __NV_SATFINITE, __NV_E4M3);
            *(uint16_t*)&BT[(size_t)row * NN + col]       = (uint16_t)(q00 | (q01 << 8));
            *(uint16_t*)&BT[(size_t)(row + 8) * NN + col] = (uint16_t)(q10 | (q11 << 8));
        }
    }
}

// combine split-K partials: h1 = relu(p0 + p1 + bias) -> fp16 row-major
__global__ void combine_relu_h(const float* __restrict__ p, const float* __restrict__ bias,
                               __half* __restrict__ C, int Ncols)
{
    const size_t i = ((size_t)blockIdx.x * blockDim.x + threadIdx.x) * 4;
    const int col = (int)(i % Ncols);
    float4 a = *(const float4*)(p + i);
    float4 b = *(const float4*)(p + (size_t)NN * Ncols + i);
    float4 bv = *(const float4*)(bias + col);
    __half2 h0 = __floats2half2_rn(fmaxf(a.x + b.x + bv.x, 0.f),
                                   fmaxf(a.y + b.y + bv.y, 0.f));
    __half2 h1 = __floats2half2_rn(fmaxf(a.z + b.z + bv.z, 0.f),
                                   fmaxf(a.w + b.w + bv.w, 0.f));
    *(__half2*)&C[i]     = h0;
    *(__half2*)&C[i + 2] = h1;
}

// =================== pooling + head ========================================
__global__ void colpart_k(const float* __restrict__ h2, float* __restrict__ part)
{
    const int b = blockIdx.x;
    const int t = threadIdx.x;
    const float* base = h2 + (size_t)b * 64 * NH2;
    float s0 = 0.f, s1 = 0.f;
    #pragma unroll 4
    for (int r = 0; r < 64; r++) {
        s0 += base[r * NH2 + t];
        s1 += base[r * NH2 + t + 256];
    }
    part[b * NH2 + t]       = s0;
    part[b * NH2 + t + 256] = s1;
}

__global__ void head_k(const float* __restrict__ part,
                       const float* __restrict__ sub_fea,
                       const float* __restrict__ fc1W, const float* __restrict__ fc1b,
                       const float* __restrict__ attW, const float* __restrict__ atta,
                       const float* __restrict__ attb, float* __restrict__ out)
{
    __shared__ float z[NZ];
    __shared__ float sc[NHEADS];
    __shared__ float alpha[NHEADS];
    __shared__ float redAll[256][NCLASS];

    const int t = threadIdx.x;

    float s0 = 0.f, s1 = 0.f;
    for (int b = 0; b < 128; b++) {
        s0 += part[b * NH2 + t];
        s1 += part[b * NH2 + t + 256];
    }
    const float selu_s = 1.0507009873554805f;
    const float selu_a = 1.6732632423543772f;
    float m0 = s0 * (1.0f / NN), m1 = s1 * (1.0f / NN);
    z[t]       = (m0 > 0.f) ? selu_s * m0 : selu_s * selu_a * (expf(m0) - 1.f);
    z[t + 256] = (m1 > 0.f) ? selu_s * m1 : selu_s * selu_a * (expf(m1) - 1.f);

    float xe = fc1b[t];
    #pragma unroll 4
    for (int i = 0; i < NFEXT; i++)
        xe = fmaf(sub_fea[i], fc1W[i * NHID + t], xe);
    z[512 + t] = xe;
    __syncthreads();

    const int w = t >> 5, lane = t & 31;
    if (w < NHEADS) {
        float s = 0.f;
        for (int i = lane; i < NZ; i += 32)
            s = fmaf(z[i], atta[w * NZ + i], s);
        #pragma unroll
        for (int o = 16; o > 0; o >>= 1) s += __shfl_xor_sync(0xffffffffu, s, o);
        if (lane == 0) sc[w] = s;
    }
    __syncthreads();
    if (t == 0) {
        float mx = sc[0];
        for (int h = 1; h < NHEADS; h++) mx = fmaxf(mx, sc[h]);
        float den = 0.f;
        for (int h = 0; h < NHEADS; h++) { alpha[h] = expf(sc[h] - mx); den += alpha[h]; }
        float inv = 1.f / den;
        for (int h = 0; h < NHEADS; h++) alpha[h] *= inv;
    }
    __syncthreads();

    float acc[NCLASS];
    #pragma unroll
    for (int o = 0; o < NCLASS; o++) acc[o] = 0.f;
    for (int idx = t; idx < NHEADS * NZ; idx += 256) {
        const int h = idx / NZ;
        const int i = idx - h * NZ;
        const float wz = alpha[h] * z[i];
        const float* wp = attW + (size_t)idx * NCLASS;
        #pragma unroll
        for (int o = 0; o < NCLASS; o++) acc[o] = fmaf(wz, wp[o], acc[o]);
    }
    #pragma unroll
    for (int o = 0; o < NCLASS; o++) redAll[t][o] = acc[o];
    __syncthreads();

    if (t == 0) {
        float v[NCLASS];
        float mx = -1e30f;
        for (int o = 0; o < NCLASS; o++) {
            float s = 0.f;
            for (int i = 0; i < 256; i++) s += redAll[i][o];
            v[o] = s + attb[o];
            mx = fmaxf(mx, v[o]);
        }
        float den = 0.f;
        for (int o = 0; o < NCLASS; o++) den += expf(v[o] - mx);
        float lse = logf(den) + mx;
        for (int o = 0; o < NCLASS; o++) out[o] = v[o] - lse;
    }
}

// ===========================================================================
extern "C" void kernel_launch(void* const* d_in, const int* in_sizes, int n_in,
                              void* d_out, int out_size)
{
    const float* x      = (const float*)d_in[0];
    const float* adj    = (const float*)d_in[1];
    const float* subfea = (const float*)d_in[2];
    const float* gc1W   = (const float*)d_in[3];
    const float* gc1b   = (const float*)d_in[4];
    const float* gc2W   = (const float*)d_in[5];
    const float* gc2b   = (const float*)d_in[6];
    const float* fc1W   = (const float*)d_in[7];
    const float* fc1b   = (const float*)d_in[8];
    const float* attW   = (const float*)d_in[9];
    const float* atta   = (const float*)d_in[10];
    const float* attb   = (const float*)d_in[11];
    float* out = (float*)d_out;

    uint8_t *adj8, *b1T, *b2T;
    __half *xh, *w1T, *w2T, *h1h;
    float *p1, *h2, *part;
    cudaGetSymbolAddress((void**)&adj8, g_adj8);
    cudaGetSymbolAddress((void**)&xh,   g_xh);
    cudaGetSymbolAddress((void**)&w1T,  g_w1T);
    cudaGetSymbolAddress((void**)&w2T,  g_w2T);
    cudaGetSymbolAddress((void**)&b1T,  g_b1T);
    cudaGetSymbolAddress((void**)&h1h,  g_h1h);
    cudaGetSymbolAddress((void**)&p1,   g_p1);
    cudaGetSymbolAddress((void**)&b2T,  g_b2T);
    cudaGetSymbolAddress((void**)&h2,   g_h2);
    cudaGetSymbolAddress((void**)&part, g_part);

    cudaFuncSetAttribute(mma_gemm8<true>,  cudaFuncAttributeMaxDynamicSharedMemorySize, MM_DSMEM);
    cudaFuncSetAttribute(mma_gemm8<false>, cudaFuncAttributeMaxDynamicSharedMemorySize, MM_DSMEM);
    cudaFuncSetAttribute(mma_bgen,         cudaFuncAttributeMaxDynamicSharedMemorySize, MM_DSMEM);

    // converts
    tof8_k<<<(NN * (size_t)NN) / (8 * 256), 256>>>(adj, adj8);
    tof16_k<<<(NN * (size_t)NFEAT) / (8 * 256), 256>>>(x, xh);

    // weight transposes -> fp16
    transW_k<<<dim3(NHID / 32, NFEAT / 32), dim3(32, 8)>>>(gc1W, w1T, NFEAT, NHID);
    transW_k<<<dim3(NH2 / 32, NHID / 32), dim3(32, 8)>>>(gc2W, w2T, NHID, NH2);

    // b1T[256,8192] = e4m3(W1T @ x^T)   (unit scale; values O(1))
    mma_bgen<<<dim3(NN / 128, NHID / 128), 256, MM_DSMEM>>>(w1T, xh, b1T, NFEAT, 1.0f);

    // h1 = relu(adj @ xw1 + gc1_b) — fp8 split-K x2; invscale = 1/ADJ_SCALE
    mma_gemm8<false><<<dim3(NHID / 128, NN / 128, 2), 256, MM_DSMEM>>>(
        adj8, b1T, nullptr, p1, NHID, 1.0f / ADJ_SCALE);
    combine_relu_h<<<(NN * NHID) / (4 * 256), 256>>>(p1, gc1b, h1h, NHID);

    // b2T[512,8192] = e4m3(B2_SCALE * (W2T @ h1^T))  (hw2 ~5e-3 -> scale x256)
    mma_bgen<<<dim3(NN / 128, NH2 / 128), 256, MM_DSMEM>>>(w2T, h1h, b2T, NHID, B2_SCALE);

    // h2 = relu(adj @ hw2 + gc2_b) — fp8; invscale = 1/(ADJ_SCALE*B2_SCALE)
    mma_gemm8<true><<<dim3(NH2 / 128, NN / 128), 256, MM_DSMEM>>>(
        adj8, b2T, gc2b, h2, NH2, 1.0f / (ADJ_SCALE * B2_SCALE));

    // pooling + head
    colpart_k<<<128, 256>>>(h2, part);
    head_k<<<1, 256>>>(part, subfea, fc1W, fc1b, attW, atta, attb, out);
}